// round 5
// baseline (speedup 1.0000x reference)
#include <cuda_runtime.h>
#include <cstdint>

#define D_MODEL 1024
#define NHEAD   16
#define DK      64
#define BATCH   2
#define SEQ     2048
#define MTOT    (BATCH * SEQ)   // 4096

// Scratch (device globals — no runtime allocation allowed)
__device__ float g_q[MTOT * D_MODEL];
__device__ float g_k[MTOT * D_MODEL];
__device__ float g_v[MTOT * D_MODEL];
__device__ float g_att[MTOT * D_MODEL];

// ============================================================================
// Common helpers
// ============================================================================
__device__ __forceinline__ void cp_async16(uint32_t dst, const void* src) {
    asm volatile("cp.async.ca.shared.global [%0], [%1], 16;"
                 :: "r"(dst), "l"(src) : "memory");
}
__device__ __forceinline__ void cp_commit() {
    asm volatile("cp.async.commit_group;" ::: "memory");
}
__device__ __forceinline__ void cp_wait1() {
    asm volatile("cp.async.wait_group 1;" ::: "memory");
}
__device__ __forceinline__ void cp_wait0() {
    asm volatile("cp.async.wait_group 0;" ::: "memory");
}
__device__ __forceinline__ uint32_t smem_u32(const void* p) {
    uint32_t a;
    asm("{ .reg .u64 t; cvta.to.shared.u64 t, %1; cvt.u32.u64 %0, t; }"
        : "=r"(a) : "l"(p));
    return a;
}
__device__ __forceinline__ uint32_t f2tf32r(float f) {   // round-to-nearest tf32
    uint32_t u;
    asm("cvt.rna.tf32.f32 %0, %1;" : "=r"(u) : "f"(f));
    return u;
}
__device__ __forceinline__ void split_tf32(float v, uint32_t& big, uint32_t& res) {
    uint32_t b = f2tf32r(v);
    big = b;
    res = __float_as_uint(v - __uint_as_float(b));
}
__device__ __forceinline__ void mma_tf32(float& c0, float& c1, float& c2, float& c3,
                                         uint32_t a0, uint32_t a1, uint32_t a2, uint32_t a3,
                                         uint32_t b0, uint32_t b1) {
    asm volatile(
        "mma.sync.aligned.m16n8k8.row.col.f32.tf32.tf32.f32 "
        "{%0,%1,%2,%3}, {%4,%5,%6,%7}, {%8,%9}, {%0,%1,%2,%3};"
        : "+f"(c0), "+f"(c1), "+f"(c2), "+f"(c3)
        : "r"(a0), "r"(a1), "r"(a2), "r"(a3), "r"(b0), "r"(b1));
}

// ============================================================================
// 3xTF32 GEMM:  out[M,N] = X[M,K] @ W[N,K]^T + bias[N]   (fp32-equivalent)
// BM=BN=128, BK=32, 256 thr (8 warps, 2x4), warp tile 64x32.
// ============================================================================
#define BM 128
#define BN 128
#define BK 32
#define PITCH 36
#define STAGE_FLOATS (128 * PITCH)
#define SMEM_GEMM_BYTES (4 * STAGE_FLOATS * 4)  // 73728 B

__global__ __launch_bounds__(256) void gemm_mma(
    const float* __restrict__ X, const float* __restrict__ W,
    const float* __restrict__ bias, float* __restrict__ out,
    int M, int N, int K)
{
    extern __shared__ __align__(16) float smem[];
    float* As[2] = { smem,                    smem + STAGE_FLOATS };
    float* Bs[2] = { smem + 2 * STAGE_FLOATS, smem + 3 * STAGE_FLOATS };

    const int tid  = threadIdx.x;
    const int wid  = tid >> 5;
    const int lane = tid & 31;
    const int gq   = lane >> 2;
    const int tq   = lane & 3;
    const int warp_m = (wid & 1) * 64;
    const int warp_n = (wid >> 1) * 32;
    const int m0 = blockIdx.y * BM;
    const int n0 = blockIdx.x * BN;

    const int ldr = tid >> 3;
    const int ldc = (tid & 7) * 4;
    const float* Xp = X + (size_t)(m0 + ldr) * K + ldc;
    const float* Wp = W + (size_t)(n0 + ldr) * K + ldc;
    const uint32_t aBase[2] = { smem_u32(As[0]), smem_u32(As[1]) };
    const uint32_t bBase[2] = { smem_u32(Bs[0]), smem_u32(Bs[1]) };
    const uint32_t dstOff = (uint32_t)(ldr * PITCH + ldc) * 4;

    float c[4][4][4];
    #pragma unroll
    for (int i = 0; i < 4; i++)
        #pragma unroll
        for (int j = 0; j < 4; j++) {
            c[i][j][0] = 0.f; c[i][j][1] = 0.f; c[i][j][2] = 0.f; c[i][j][3] = 0.f;
        }

    const int NT = K / BK;

    #pragma unroll
    for (int i = 0; i < 4; i++) {
        uint32_t d = dstOff + (uint32_t)(i * 32 * PITCH * 4);
        cp_async16(aBase[0] + d, Xp + (size_t)i * 32 * K);
        cp_async16(bBase[0] + d, Wp + (size_t)i * 32 * K);
    }
    cp_commit();

    int buf = 0;
    for (int kt = 0; kt < NT; kt++) {
        if (kt + 1 < NT) {
            const float* xs = Xp + (kt + 1) * BK;
            const float* ws = Wp + (kt + 1) * BK;
            const int nb = buf ^ 1;
            #pragma unroll
            for (int i = 0; i < 4; i++) {
                uint32_t d = dstOff + (uint32_t)(i * 32 * PITCH * 4);
                cp_async16(aBase[nb] + d, xs + (size_t)i * 32 * K);
                cp_async16(bBase[nb] + d, ws + (size_t)i * 32 * K);
            }
            cp_commit();
            cp_wait1();
        } else {
            cp_wait0();
        }
        __syncthreads();

        const float* Af = As[buf];
        const float* Bf = Bs[buf];
        #pragma unroll
        for (int s = 0; s < 4; s++) {
            const int k0 = s * 8;
            uint32_t b0b[4], b0r[4], b1b[4], b1r[4];
            #pragma unroll
            for (int nt = 0; nt < 4; nt++) {
                const float* bp = Bf + (warp_n + nt * 8 + gq) * PITCH + k0 + tq;
                split_tf32(bp[0], b0b[nt], b0r[nt]);
                split_tf32(bp[4], b1b[nt], b1r[nt]);
            }
            #pragma unroll
            for (int mt = 0; mt < 4; mt++) {
                const float* ap = Af + (warp_m + mt * 16 + gq) * PITCH + k0 + tq;
                uint32_t ab[4], ar[4];
                split_tf32(ap[0],             ab[0], ar[0]);
                split_tf32(ap[8 * PITCH],     ab[1], ar[1]);
                split_tf32(ap[4],             ab[2], ar[2]);
                split_tf32(ap[8 * PITCH + 4], ab[3], ar[3]);
                #pragma unroll
                for (int nt = 0; nt < 4; nt++) {
                    mma_tf32(c[mt][nt][0], c[mt][nt][1], c[mt][nt][2], c[mt][nt][3],
                             ab[0], ab[1], ab[2], ab[3], b0b[nt], b1b[nt]);
                    mma_tf32(c[mt][nt][0], c[mt][nt][1], c[mt][nt][2], c[mt][nt][3],
                             ab[0], ab[1], ab[2], ab[3], b0r[nt], b1r[nt]);
                    mma_tf32(c[mt][nt][0], c[mt][nt][1], c[mt][nt][2], c[mt][nt][3],
                             ar[0], ar[1], ar[2], ar[3], b0b[nt], b1b[nt]);
                }
            }
        }
        __syncthreads();
        buf ^= 1;
    }

    #pragma unroll
    for (int mt = 0; mt < 4; mt++) {
        const int r0 = m0 + warp_m + mt * 16 + gq;
        #pragma unroll
        for (int nt = 0; nt < 4; nt++) {
            const int col = n0 + warp_n + nt * 8 + tq * 2;
            const float bv0 = bias[col], bv1 = bias[col + 1];
            float2 u, v;
            u.x = c[mt][nt][0] + bv0; u.y = c[mt][nt][1] + bv1;
            v.x = c[mt][nt][2] + bv0; v.y = c[mt][nt][3] + bv1;
            *(float2*)&out[(size_t)r0 * N + col] = u;
            *(float2*)&out[(size_t)(r0 + 8) * N + col] = v;
        }
    }
}

// ============================================================================
// Flash attention v2 (tf32 mma.sync, high accuracy):
//  - S = Qb @ (Kb + Kr)      (K truncation error removed; Q-only residual)
//  - P rounded to tf32, normalizer l computed from ROUNDED P (consistency)
//  - O += P @ (Vb + Vr)      (V truncation error removed)
//  - C->A fragment conversion via shfl (no S smem buffer, smem 70KB -> 3 CTA/SM)
// CTA = 128 thr = 4 warps, one (b,h,64-query tile). Warp owns 16 query rows.
// ============================================================================
#define AT_KP 68
#define AT_VP 72
#define AT_KS0 0
#define AT_KS1 (64 * AT_KP)
#define AT_VS0 (2 * 64 * AT_KP)
#define AT_VS1 (2 * 64 * AT_KP + 64 * AT_VP)
#define AT_SMEM_BYTES ((2 * 64 * AT_KP + 2 * 64 * AT_VP) * 4)   // 71680

__global__ __launch_bounds__(128, 3) void attn_mma(
    const float* __restrict__ Qp, const float* __restrict__ Kp,
    const float* __restrict__ Vp, float* __restrict__ Op)
{
    extern __shared__ __align__(16) float sm[];
    const int tid  = threadIdx.x;
    const int wid  = tid >> 5;
    const int lane = tid & 31;
    const int gq   = lane >> 2;
    const int tq   = lane & 3;
    const int warp_m = wid * 16;
    const int bh = blockIdx.y;
    const int b  = bh >> 4;
    const int h  = bh & 15;
    const int q0 = blockIdx.x * 64;

    const float* Qb = Qp + (size_t)(b * SEQ + q0) * D_MODEL + h * DK;
    const float* Kb = Kp + (size_t)(b * SEQ) * D_MODEL + h * DK;
    const float* Vb = Vp + (size_t)(b * SEQ) * D_MODEL + h * DK;

    // Q fragments (big part only), pre-scaled by 1/sqrt(dk)=1/8, rna-rounded.
    uint32_t qa[8][4];
    #pragma unroll
    for (int ks = 0; ks < 8; ks++) {
        const float* qp = Qb + (size_t)(warp_m + gq) * D_MODEL + ks * 8 + tq;
        qa[ks][0] = f2tf32r(qp[0] * 0.125f);
        qa[ks][1] = f2tf32r(qp[8 * D_MODEL] * 0.125f);
        qa[ks][2] = f2tf32r(qp[4] * 0.125f);
        qa[ks][3] = f2tf32r(qp[8 * D_MODEL + 4] * 0.125f);
    }

    float o[8][4];
    #pragma unroll
    for (int i = 0; i < 8; i++) { o[i][0] = 0.f; o[i][1] = 0.f; o[i][2] = 0.f; o[i][3] = 0.f; }
    const float NEG_INF = __int_as_float(0xff800000);
    float m0 = NEG_INF, m1 = NEG_INF, l0 = 0.f, l1 = 0.f;

    // K/V loaders: thread -> row tid>>1, float-col (tid&1)*32, 8 x 16B each.
    const int ldr = tid >> 1;
    const int ldh = (tid & 1) * 32;
    const float* Ksrc = Kb + (size_t)ldr * D_MODEL + ldh;
    const float* Vsrc = Vb + (size_t)ldr * D_MODEL + ldh;
    const uint32_t smb = smem_u32(sm);
    const uint32_t kdst0 = smb + (uint32_t)((AT_KS0 + ldr * AT_KP + ldh) * 4);
    const uint32_t kdst1 = smb + (uint32_t)((AT_KS1 + ldr * AT_KP + ldh) * 4);
    const uint32_t vdst0 = smb + (uint32_t)((AT_VS0 + ldr * AT_VP + ldh) * 4);
    const uint32_t vdst1 = smb + (uint32_t)((AT_VS1 + ldr * AT_VP + ldh) * 4);

    #pragma unroll
    for (int i = 0; i < 8; i++) {
        cp_async16(kdst0 + i * 16, Ksrc + i * 4);
        cp_async16(vdst0 + i * 16, Vsrc + i * 4);
    }
    cp_commit();

    // shfl source lanes for C->A fragment conversion
    const int srcl0 = gq * 4 + (tq >> 1);
    const int srcl1 = srcl0 + 2;
    const bool odd = (tq & 1);

    for (int kt = 0; kt < SEQ / 64; kt++) {
        const int buf = kt & 1;
        if (kt + 1 < SEQ / 64) {
            const float* ks2 = Ksrc + (size_t)(kt + 1) * 64 * D_MODEL;
            const float* vs2 = Vsrc + (size_t)(kt + 1) * 64 * D_MODEL;
            const uint32_t kd = buf ? kdst0 : kdst1;
            const uint32_t vd = buf ? vdst0 : vdst1;
            #pragma unroll
            for (int i = 0; i < 8; i++) {
                cp_async16(kd + i * 16, ks2 + i * 4);
                cp_async16(vd + i * 16, vs2 + i * 4);
            }
            cp_commit();
            cp_wait1();
        } else {
            cp_wait0();
        }
        __syncthreads();

        const float* Kst = sm + (buf ? AT_KS1 : AT_KS0);
        const float* Vst = sm + (buf ? AT_VS1 : AT_VS0);

        // ---- S = Qb @ (Kb + Kr) : 2-term, K truncation removed
        float s[8][4];
        #pragma unroll
        for (int i = 0; i < 8; i++) { s[i][0] = 0.f; s[i][1] = 0.f; s[i][2] = 0.f; s[i][3] = 0.f; }
        #pragma unroll
        for (int ks = 0; ks < 8; ks++) {
            uint32_t kb0[8], kb1[8], kr0[8], kr1[8];
            #pragma unroll
            for (int nf = 0; nf < 8; nf++) {
                const float* kp = Kst + (nf * 8 + gq) * AT_KP + ks * 8 + tq;
                split_tf32(kp[0], kb0[nf], kr0[nf]);
                split_tf32(kp[4], kb1[nf], kr1[nf]);
            }
            #pragma unroll
            for (int nf = 0; nf < 8; nf++) {
                mma_tf32(s[nf][0], s[nf][1], s[nf][2], s[nf][3],
                         qa[ks][0], qa[ks][1], qa[ks][2], qa[ks][3], kb0[nf], kb1[nf]);
                mma_tf32(s[nf][0], s[nf][1], s[nf][2], s[nf][3],
                         qa[ks][0], qa[ks][1], qa[ks][2], qa[ks][3], kr0[nf], kr1[nf]);
            }
        }

        // ---- online softmax (row gq -> c0,c1 ; row gq+8 -> c2,c3)
        float mx0 = NEG_INF, mx1 = NEG_INF;
        #pragma unroll
        for (int nf = 0; nf < 8; nf++) {
            mx0 = fmaxf(mx0, fmaxf(s[nf][0], s[nf][1]));
            mx1 = fmaxf(mx1, fmaxf(s[nf][2], s[nf][3]));
        }
        mx0 = fmaxf(mx0, __shfl_xor_sync(0xffffffff, mx0, 1));
        mx0 = fmaxf(mx0, __shfl_xor_sync(0xffffffff, mx0, 2));
        mx1 = fmaxf(mx1, __shfl_xor_sync(0xffffffff, mx1, 1));
        mx1 = fmaxf(mx1, __shfl_xor_sync(0xffffffff, mx1, 2));
        const float m0n = fmaxf(m0, mx0);
        const float m1n = fmaxf(m1, mx1);
        const float fac0 = __expf(m0 - m0n);
        const float fac1 = __expf(m1 - m1n);
        float sum0 = 0.f, sum1 = 0.f;
        // exp, round P to tf32, and accumulate l from the ROUNDED values
        #pragma unroll
        for (int nf = 0; nf < 8; nf++) {
            s[nf][0] = __uint_as_float(f2tf32r(__expf(s[nf][0] - m0n)));
            s[nf][1] = __uint_as_float(f2tf32r(__expf(s[nf][1] - m0n)));
            s[nf][2] = __uint_as_float(f2tf32r(__expf(s[nf][2] - m1n)));
            s[nf][3] = __uint_as_float(f2tf32r(__expf(s[nf][3] - m1n)));
            sum0 += s[nf][0] + s[nf][1];
            sum1 += s[nf][2] + s[nf][3];
        }
        sum0 += __shfl_xor_sync(0xffffffff, sum0, 1);
        sum0 += __shfl_xor_sync(0xffffffff, sum0, 2);
        sum1 += __shfl_xor_sync(0xffffffff, sum1, 1);
        sum1 += __shfl_xor_sync(0xffffffff, sum1, 2);
        m0 = m0n; m1 = m1n;
        l0 = l0 * fac0 + sum0;
        l1 = l1 * fac1 + sum1;

        // ---- rescale O
        #pragma unroll
        for (int nf = 0; nf < 8; nf++) {
            o[nf][0] *= fac0; o[nf][1] *= fac0;
            o[nf][2] *= fac1; o[nf][3] *= fac1;
        }

        // ---- O += P @ (Vb + Vr) : A-fragments built from s[] via shfl
        #pragma unroll
        for (int ks = 0; ks < 8; ks++) {
            const float u0 = __shfl_sync(0xffffffff, s[ks][0], srcl0);
            const float u1 = __shfl_sync(0xffffffff, s[ks][1], srcl0);
            const float u2 = __shfl_sync(0xffffffff, s[ks][2], srcl0);
            const float u3 = __shfl_sync(0xffffffff, s[ks][3], srcl0);
            const float u4 = __shfl_sync(0xffffffff, s[ks][0], srcl1);
            const float u5 = __shfl_sync(0xffffffff, s[ks][1], srcl1);
            const float u6 = __shfl_sync(0xffffffff, s[ks][2], srcl1);
            const float u7 = __shfl_sync(0xffffffff, s[ks][3], srcl1);
            const uint32_t pa0 = __float_as_uint(odd ? u1 : u0);
            const uint32_t pa1 = __float_as_uint(odd ? u3 : u2);
            const uint32_t pa2 = __float_as_uint(odd ? u5 : u4);
            const uint32_t pa3 = __float_as_uint(odd ? u7 : u6);

            uint32_t vb0[8], vb1[8], vr0[8], vr1[8];
            #pragma unroll
            for (int nf = 0; nf < 8; nf++) {
                const float* vp = Vst + (ks * 8 + tq) * AT_VP + nf * 8 + gq;
                split_tf32(vp[0],           vb0[nf], vr0[nf]);
                split_tf32(vp[4 * AT_VP],   vb1[nf], vr1[nf]);
            }
            #pragma unroll
            for (int nf = 0; nf < 8; nf++) {
                mma_tf32(o[nf][0], o[nf][1], o[nf][2], o[nf][3],
                         pa0, pa1, pa2, pa3, vb0[nf], vb1[nf]);
                mma_tf32(o[nf][0], o[nf][1], o[nf][2], o[nf][3],
                         pa0, pa1, pa2, pa3, vr0[nf], vr1[nf]);
            }
        }
        __syncthreads();
    }

    // ---- epilogue: normalize and store
    const float inv0 = 1.f / l0;
    const float inv1 = 1.f / l1;
    float* Ob = Op + (size_t)(b * SEQ + q0 + warp_m + gq) * D_MODEL + h * DK;
    #pragma unroll
    for (int nf = 0; nf < 8; nf++) {
        float2 u, v;
        u.x = o[nf][0] * inv0; u.y = o[nf][1] * inv0;
        v.x = o[nf][2] * inv1; v.y = o[nf][3] * inv1;
        *(float2*)(Ob + nf * 8 + tq * 2) = u;
        *(float2*)(Ob + (size_t)8 * D_MODEL + nf * 8 + tq * 2) = v;
    }
}

// ============================================================================
// Launcher
// ============================================================================
extern "C" void kernel_launch(void* const* d_in, const int* in_sizes, int n_in,
                              void* d_out, int out_size)
{
    const float* q    = (const float*)d_in[0];
    const float* k    = (const float*)d_in[1];
    const float* v    = (const float*)d_in[2];
    const float* wq_w = (const float*)d_in[3];
    const float* wq_b = (const float*)d_in[4];
    const float* wk_w = (const float*)d_in[5];
    const float* wk_b = (const float*)d_in[6];
    const float* wv_w = (const float*)d_in[7];
    const float* wv_b = (const float*)d_in[8];
    const float* wo_w = (const float*)d_in[9];
    const float* wo_b = (const float*)d_in[10];

    float *gq, *gk, *gv, *ga;
    cudaGetSymbolAddress((void**)&gq, g_q);
    cudaGetSymbolAddress((void**)&gk, g_k);
    cudaGetSymbolAddress((void**)&gv, g_v);
    cudaGetSymbolAddress((void**)&ga, g_att);

    cudaFuncSetAttribute(gemm_mma, cudaFuncAttributeMaxDynamicSharedMemorySize,
                         SMEM_GEMM_BYTES);
    cudaFuncSetAttribute(attn_mma, cudaFuncAttributeMaxDynamicSharedMemorySize,
                         AT_SMEM_BYTES);

    dim3 gemm_grid(D_MODEL / BN, MTOT / BM);   // (8, 32)

    gemm_mma<<<gemm_grid, 256, SMEM_GEMM_BYTES>>>(q, wq_w, wq_b, gq, MTOT, D_MODEL, D_MODEL);
    gemm_mma<<<gemm_grid, 256, SMEM_GEMM_BYTES>>>(k, wk_w, wk_b, gk, MTOT, D_MODEL, D_MODEL);
    gemm_mma<<<gemm_grid, 256, SMEM_GEMM_BYTES>>>(v, wv_w, wv_b, gv, MTOT, D_MODEL, D_MODEL);

    attn_mma<<<dim3(SEQ / 64, BATCH * NHEAD), 128, AT_SMEM_BYTES>>>(gq, gk, gv, ga);

    gemm_mma<<<gemm_grid, 256, SMEM_GEMM_BYTES>>>(ga, wo_w, wo_b, (float*)d_out, MTOT, D_MODEL, D_MODEL);
}

// round 7
// speedup vs baseline: 1.0913x; 1.0913x over previous
#include <cuda_runtime.h>
#include <cstdint>

#define D_MODEL 1024
#define NHEAD   16
#define DK      64
#define BATCH   2
#define SEQ     2048
#define MTOT    (BATCH * SEQ)   // 4096

// Scratch (device globals — no runtime allocation allowed)
__device__ float g_q[MTOT * D_MODEL];
__device__ float g_k[MTOT * D_MODEL];
__device__ float g_v[MTOT * D_MODEL];
__device__ float g_att[MTOT * D_MODEL];

// ============================================================================
// Common helpers
// ============================================================================
__device__ __forceinline__ void cp_async16(uint32_t dst, const void* src) {
    asm volatile("cp.async.ca.shared.global [%0], [%1], 16;"
                 :: "r"(dst), "l"(src) : "memory");
}
__device__ __forceinline__ void cp_commit() {
    asm volatile("cp.async.commit_group;" ::: "memory");
}
__device__ __forceinline__ void cp_wait1() {
    asm volatile("cp.async.wait_group 1;" ::: "memory");
}
__device__ __forceinline__ void cp_wait0() {
    asm volatile("cp.async.wait_group 0;" ::: "memory");
}
__device__ __forceinline__ uint32_t smem_u32(const void* p) {
    uint32_t a;
    asm("{ .reg .u64 t; cvta.to.shared.u64 t, %1; cvt.u32.u64 %0, t; }"
        : "=r"(a) : "l"(p));
    return a;
}
__device__ __forceinline__ uint32_t f2tf32r(float f) {   // round-to-nearest tf32
    uint32_t u;
    asm("cvt.rna.tf32.f32 %0, %1;" : "=r"(u) : "f"(f));
    return u;
}
__device__ __forceinline__ void split_tf32(float v, uint32_t& big, uint32_t& res) {
    uint32_t b = f2tf32r(v);
    big = b;
    res = __float_as_uint(v - __uint_as_float(b));
}
__device__ __forceinline__ void mma_tf32(float& c0, float& c1, float& c2, float& c3,
                                         uint32_t a0, uint32_t a1, uint32_t a2, uint32_t a3,
                                         uint32_t b0, uint32_t b1) {
    asm volatile(
        "mma.sync.aligned.m16n8k8.row.col.f32.tf32.tf32.f32 "
        "{%0,%1,%2,%3}, {%4,%5,%6,%7}, {%8,%9}, {%0,%1,%2,%3};"
        : "+f"(c0), "+f"(c1), "+f"(c2), "+f"(c3)
        : "r"(a0), "r"(a1), "r"(a2), "r"(a3), "r"(b0), "r"(b1));
}

// ============================================================================
// 3xTF32 GEMM:  out[M,N] = X[M,K] @ W[N,K]^T + bias[N]   (fp32-equivalent)
// BM=BN=128, BK=32, 256 thr (8 warps, 2x4), warp tile 64x32.
// ============================================================================
#define BM 128
#define BN 128
#define BK 32
#define PITCH 36
#define STAGE_FLOATS (128 * PITCH)
#define SMEM_GEMM_BYTES (4 * STAGE_FLOATS * 4)  // 73728 B

__global__ __launch_bounds__(256) void gemm_mma(
    const float* __restrict__ X, const float* __restrict__ W,
    const float* __restrict__ bias, float* __restrict__ out,
    int M, int N, int K)
{
    extern __shared__ __align__(16) float smem[];
    float* As[2] = { smem,                    smem + STAGE_FLOATS };
    float* Bs[2] = { smem + 2 * STAGE_FLOATS, smem + 3 * STAGE_FLOATS };

    const int tid  = threadIdx.x;
    const int wid  = tid >> 5;
    const int lane = tid & 31;
    const int gq   = lane >> 2;
    const int tq   = lane & 3;
    const int warp_m = (wid & 1) * 64;
    const int warp_n = (wid >> 1) * 32;
    const int m0 = blockIdx.y * BM;
    const int n0 = blockIdx.x * BN;

    const int ldr = tid >> 3;
    const int ldc = (tid & 7) * 4;
    const float* Xp = X + (size_t)(m0 + ldr) * K + ldc;
    const float* Wp = W + (size_t)(n0 + ldr) * K + ldc;
    const uint32_t aBase[2] = { smem_u32(As[0]), smem_u32(As[1]) };
    const uint32_t bBase[2] = { smem_u32(Bs[0]), smem_u32(Bs[1]) };
    const uint32_t dstOff = (uint32_t)(ldr * PITCH + ldc) * 4;

    float c[4][4][4];
    #pragma unroll
    for (int i = 0; i < 4; i++)
        #pragma unroll
        for (int j = 0; j < 4; j++) {
            c[i][j][0] = 0.f; c[i][j][1] = 0.f; c[i][j][2] = 0.f; c[i][j][3] = 0.f;
        }

    const int NT = K / BK;

    #pragma unroll
    for (int i = 0; i < 4; i++) {
        uint32_t d = dstOff + (uint32_t)(i * 32 * PITCH * 4);
        cp_async16(aBase[0] + d, Xp + (size_t)i * 32 * K);
        cp_async16(bBase[0] + d, Wp + (size_t)i * 32 * K);
    }
    cp_commit();

    int buf = 0;
    for (int kt = 0; kt < NT; kt++) {
        if (kt + 1 < NT) {
            const float* xs = Xp + (kt + 1) * BK;
            const float* ws = Wp + (kt + 1) * BK;
            const int nb = buf ^ 1;
            #pragma unroll
            for (int i = 0; i < 4; i++) {
                uint32_t d = dstOff + (uint32_t)(i * 32 * PITCH * 4);
                cp_async16(aBase[nb] + d, xs + (size_t)i * 32 * K);
                cp_async16(bBase[nb] + d, ws + (size_t)i * 32 * K);
            }
            cp_commit();
            cp_wait1();
        } else {
            cp_wait0();
        }
        __syncthreads();

        const float* Af = As[buf];
        const float* Bf = Bs[buf];
        #pragma unroll
        for (int s = 0; s < 4; s++) {
            const int k0 = s * 8;
            uint32_t b0b[4], b0r[4], b1b[4], b1r[4];
            #pragma unroll
            for (int nt = 0; nt < 4; nt++) {
                const float* bp = Bf + (warp_n + nt * 8 + gq) * PITCH + k0 + tq;
                split_tf32(bp[0], b0b[nt], b0r[nt]);
                split_tf32(bp[4], b1b[nt], b1r[nt]);
            }
            #pragma unroll
            for (int mt = 0; mt < 4; mt++) {
                const float* ap = Af + (warp_m + mt * 16 + gq) * PITCH + k0 + tq;
                uint32_t ab[4], ar[4];
                split_tf32(ap[0],             ab[0], ar[0]);
                split_tf32(ap[8 * PITCH],     ab[1], ar[1]);
                split_tf32(ap[4],             ab[2], ar[2]);
                split_tf32(ap[8 * PITCH + 4], ab[3], ar[3]);
                #pragma unroll
                for (int nt = 0; nt < 4; nt++) {
                    mma_tf32(c[mt][nt][0], c[mt][nt][1], c[mt][nt][2], c[mt][nt][3],
                             ab[0], ab[1], ab[2], ab[3], b0b[nt], b1b[nt]);
                    mma_tf32(c[mt][nt][0], c[mt][nt][1], c[mt][nt][2], c[mt][nt][3],
                             ab[0], ab[1], ab[2], ab[3], b0r[nt], b1r[nt]);
                    mma_tf32(c[mt][nt][0], c[mt][nt][1], c[mt][nt][2], c[mt][nt][3],
                             ar[0], ar[1], ar[2], ar[3], b0b[nt], b1b[nt]);
                }
            }
        }
        __syncthreads();
        buf ^= 1;
    }

    #pragma unroll
    for (int mt = 0; mt < 4; mt++) {
        const int r0 = m0 + warp_m + mt * 16 + gq;
        #pragma unroll
        for (int nt = 0; nt < 4; nt++) {
            const int col = n0 + warp_n + nt * 8 + tq * 2;
            const float bv0 = bias[col], bv1 = bias[col + 1];
            float2 u, v;
            u.x = c[mt][nt][0] + bv0; u.y = c[mt][nt][1] + bv1;
            v.x = c[mt][nt][2] + bv0; v.y = c[mt][nt][3] + bv1;
            *(float2*)&out[(size_t)r0 * N + col] = u;
            *(float2*)&out[(size_t)(r0 + 8) * N + col] = v;
        }
    }
}

// ============================================================================
// Flash attention v3 (tf32 mma.sync):
//  - S = Qb@K_raw + Qr@K_raw  (Q split ONCE to registers; K implicit-RZ by the
//    MMA -> Q truncation cancels exactly, zero inner-loop split ALU)
//  - P rounded rna, normalizer l computed from ROUNDED P (consistency)
//  - O += P @ V_raw           (V implicit-RZ, sign-random error)
//  - C->A fragment conversion via shfl (no S smem buffer), 3 CTAs/SM
// CTA = 128 thr = 4 warps, one (b,h,64-query tile). Warp owns 16 query rows.
// ============================================================================
#define AT_KP 68
#define AT_VP 72
#define AT_KS0 0
#define AT_KS1 (64 * AT_KP)
#define AT_VS0 (2 * 64 * AT_KP)
#define AT_VS1 (2 * 64 * AT_KP + 64 * AT_VP)
#define AT_SMEM_BYTES ((2 * 64 * AT_KP + 2 * 64 * AT_VP) * 4)   // 71680

__global__ __launch_bounds__(128, 3) void attn_mma(
    const float* __restrict__ Qp, const float* __restrict__ Kp,
    const float* __restrict__ Vp, float* __restrict__ Op)
{
    extern __shared__ __align__(16) float sm[];
    const int tid  = threadIdx.x;
    const int wid  = tid >> 5;
    const int lane = tid & 31;
    const int gq   = lane >> 2;
    const int tq   = lane & 3;
    const int warp_m = wid * 16;
    const int bh = blockIdx.y;
    const int b  = bh >> 4;
    const int h  = bh & 15;
    const int q0 = blockIdx.x * 64;

    const float* Qb = Qp + (size_t)(b * SEQ + q0) * D_MODEL + h * DK;
    const float* Kb = Kp + (size_t)(b * SEQ) * D_MODEL + h * DK;
    const float* Vb = Vp + (size_t)(b * SEQ) * D_MODEL + h * DK;

    // Q fragments split big+res ONCE (pre-scaled 1/8). Qb+Qr = Q exactly.
    uint32_t qab[8][4], qar[8][4];
    #pragma unroll
    for (int ks = 0; ks < 8; ks++) {
        const float* qp = Qb + (size_t)(warp_m + gq) * D_MODEL + ks * 8 + tq;
        split_tf32(qp[0] * 0.125f,               qab[ks][0], qar[ks][0]);
        split_tf32(qp[8 * D_MODEL] * 0.125f,     qab[ks][1], qar[ks][1]);
        split_tf32(qp[4] * 0.125f,               qab[ks][2], qar[ks][2]);
        split_tf32(qp[8 * D_MODEL + 4] * 0.125f, qab[ks][3], qar[ks][3]);
    }

    float o[8][4];
    #pragma unroll
    for (int i = 0; i < 8; i++) { o[i][0] = 0.f; o[i][1] = 0.f; o[i][2] = 0.f; o[i][3] = 0.f; }
    const float NEG_INF = __int_as_float(0xff800000);
    float m0 = NEG_INF, m1 = NEG_INF, l0 = 0.f, l1 = 0.f;

    // K/V loaders: thread -> row tid>>1, float-col (tid&1)*32, 8 x 16B each.
    const int ldr = tid >> 1;
    const int ldh = (tid & 1) * 32;
    const float* Ksrc = Kb + (size_t)ldr * D_MODEL + ldh;
    const float* Vsrc = Vb + (size_t)ldr * D_MODEL + ldh;
    const uint32_t smb = smem_u32(sm);
    const uint32_t kdst0 = smb + (uint32_t)((AT_KS0 + ldr * AT_KP + ldh) * 4);
    const uint32_t kdst1 = smb + (uint32_t)((AT_KS1 + ldr * AT_KP + ldh) * 4);
    const uint32_t vdst0 = smb + (uint32_t)((AT_VS0 + ldr * AT_VP + ldh) * 4);
    const uint32_t vdst1 = smb + (uint32_t)((AT_VS1 + ldr * AT_VP + ldh) * 4);

    #pragma unroll
    for (int i = 0; i < 8; i++) {
        cp_async16(kdst0 + i * 16, Ksrc + i * 4);
        cp_async16(vdst0 + i * 16, Vsrc + i * 4);
    }
    cp_commit();

    // shfl source lanes for C->A fragment conversion
    const int srcl0 = gq * 4 + (tq >> 1);
    const int srcl1 = srcl0 + 2;
    const bool odd = (tq & 1);

    for (int kt = 0; kt < SEQ / 64; kt++) {
        const int buf = kt & 1;
        if (kt + 1 < SEQ / 64) {
            const float* ks2 = Ksrc + (size_t)(kt + 1) * 64 * D_MODEL;
            const float* vs2 = Vsrc + (size_t)(kt + 1) * 64 * D_MODEL;
            const uint32_t kd = buf ? kdst0 : kdst1;
            const uint32_t vd = buf ? vdst0 : vdst1;
            #pragma unroll
            for (int i = 0; i < 8; i++) {
                cp_async16(kd + i * 16, ks2 + i * 4);
                cp_async16(vd + i * 16, vs2 + i * 4);
            }
            cp_commit();
            cp_wait1();
        } else {
            cp_wait0();
        }
        __syncthreads();

        const float* Kst = sm + (buf ? AT_KS1 : AT_KS0);
        const float* Vst = sm + (buf ? AT_VS1 : AT_VS0);

        // ---- S = (Qb + Qr) @ K_raw : K truncated RZ by HW, Q error cancels
        float s[8][4];
        #pragma unroll
        for (int i = 0; i < 8; i++) { s[i][0] = 0.f; s[i][1] = 0.f; s[i][2] = 0.f; s[i][3] = 0.f; }
        #pragma unroll
        for (int ks = 0; ks < 8; ks++) {
            uint32_t kb0[8], kb1[8];
            #pragma unroll
            for (int nf = 0; nf < 8; nf++) {
                const float* kp = Kst + (nf * 8 + gq) * AT_KP + ks * 8 + tq;
                kb0[nf] = __float_as_uint(kp[0]);
                kb1[nf] = __float_as_uint(kp[4]);
            }
            #pragma unroll
            for (int nf = 0; nf < 8; nf++) {
                mma_tf32(s[nf][0], s[nf][1], s[nf][2], s[nf][3],
                         qab[ks][0], qab[ks][1], qab[ks][2], qab[ks][3], kb0[nf], kb1[nf]);
                mma_tf32(s[nf][0], s[nf][1], s[nf][2], s[nf][3],
                         qar[ks][0], qar[ks][1], qar[ks][2], qar[ks][3], kb0[nf], kb1[nf]);
            }
        }

        // ---- online softmax (row gq -> c0,c1 ; row gq+8 -> c2,c3)
        float mx0 = NEG_INF, mx1 = NEG_INF;
        #pragma unroll
        for (int nf = 0; nf < 8; nf++) {
            mx0 = fmaxf(mx0, fmaxf(s[nf][0], s[nf][1]));
            mx1 = fmaxf(mx1, fmaxf(s[nf][2], s[nf][3]));
        }
        mx0 = fmaxf(mx0, __shfl_xor_sync(0xffffffff, mx0, 1));
        mx0 = fmaxf(mx0, __shfl_xor_sync(0xffffffff, mx0, 2));
        mx1 = fmaxf(mx1, __shfl_xor_sync(0xffffffff, mx1, 1));
        mx1 = fmaxf(mx1, __shfl_xor_sync(0xffffffff, mx1, 2));
        const float m0n = fmaxf(m0, mx0);
        const float m1n = fmaxf(m1, mx1);
        const float fac0 = __expf(m0 - m0n);
        const float fac1 = __expf(m1 - m1n);
        float sum0 = 0.f, sum1 = 0.f;
        // exp, round P to tf32 (rna), accumulate l from the ROUNDED values
        #pragma unroll
        for (int nf = 0; nf < 8; nf++) {
            s[nf][0] = __uint_as_float(f2tf32r(__expf(s[nf][0] - m0n)));
            s[nf][1] = __uint_as_float(f2tf32r(__expf(s[nf][1] - m0n)));
            s[nf][2] = __uint_as_float(f2tf32r(__expf(s[nf][2] - m1n)));
            s[nf][3] = __uint_as_float(f2tf32r(__expf(s[nf][3] - m1n)));
            sum0 += s[nf][0] + s[nf][1];
            sum1 += s[nf][2] + s[nf][3];
        }
        sum0 += __shfl_xor_sync(0xffffffff, sum0, 1);
        sum0 += __shfl_xor_sync(0xffffffff, sum0, 2);
        sum1 += __shfl_xor_sync(0xffffffff, sum1, 1);
        sum1 += __shfl_xor_sync(0xffffffff, sum1, 2);
        m0 = m0n; m1 = m1n;
        l0 = l0 * fac0 + sum0;
        l1 = l1 * fac1 + sum1;

        // ---- rescale O
        #pragma unroll
        for (int nf = 0; nf < 8; nf++) {
            o[nf][0] *= fac0; o[nf][1] *= fac0;
            o[nf][2] *= fac1; o[nf][3] *= fac1;
        }

        // ---- O += P @ V_raw : A-fragments built from s[] via shfl
        #pragma unroll
        for (int ks = 0; ks < 8; ks++) {
            const float u0 = __shfl_sync(0xffffffff, s[ks][0], srcl0);
            const float u1 = __shfl_sync(0xffffffff, s[ks][1], srcl0);
            const float u2 = __shfl_sync(0xffffffff, s[ks][2], srcl0);
            const float u3 = __shfl_sync(0xffffffff, s[ks][3], srcl0);
            const float u4 = __shfl_sync(0xffffffff, s[ks][0], srcl1);
            const float u5 = __shfl_sync(0xffffffff, s[ks][1], srcl1);
            const float u6 = __shfl_sync(0xffffffff, s[ks][2], srcl1);
            const float u7 = __shfl_sync(0xffffffff, s[ks][3], srcl1);
            const uint32_t pa0 = __float_as_uint(odd ? u1 : u0);
            const uint32_t pa1 = __float_as_uint(odd ? u3 : u2);
            const uint32_t pa2 = __float_as_uint(odd ? u5 : u4);
            const uint32_t pa3 = __float_as_uint(odd ? u7 : u6);

            uint32_t vb0[8], vb1[8];
            #pragma unroll
            for (int nf = 0; nf < 8; nf++) {
                const float* vp = Vst + (ks * 8 + tq) * AT_VP + nf * 8 + gq;
                vb0[nf] = __float_as_uint(vp[0]);
                vb1[nf] = __float_as_uint(vp[4 * AT_VP]);
            }
            #pragma unroll
            for (int nf = 0; nf < 8; nf++)
                mma_tf32(o[nf][0], o[nf][1], o[nf][2], o[nf][3],
                         pa0, pa1, pa2, pa3, vb0[nf], vb1[nf]);
        }
        __syncthreads();
    }

    // ---- epilogue: normalize and store
    const float inv0 = 1.f / l0;
    const float inv1 = 1.f / l1;
    float* Ob = Op + (size_t)(b * SEQ + q0 + warp_m + gq) * D_MODEL + h * DK;
    #pragma unroll
    for (int nf = 0; nf < 8; nf++) {
        float2 u, v;
        u.x = o[nf][0] * inv0; u.y = o[nf][1] * inv0;
        v.x = o[nf][2] * inv1; v.y = o[nf][3] * inv1;
        *(float2*)(Ob + nf * 8 + tq * 2) = u;
        *(float2*)(Ob + (size_t)8 * D_MODEL + nf * 8 + tq * 2) = v;
    }
}

// ============================================================================
// Launcher
// ============================================================================
extern "C" void kernel_launch(void* const* d_in, const int* in_sizes, int n_in,
                              void* d_out, int out_size)
{
    const float* q    = (const float*)d_in[0];
    const float* k    = (const float*)d_in[1];
    const float* v    = (const float*)d_in[2];
    const float* wq_w = (const float*)d_in[3];
    const float* wq_b = (const float*)d_in[4];
    const float* wk_w = (const float*)d_in[5];
    const float* wk_b = (const float*)d_in[6];
    const float* wv_w = (const float*)d_in[7];
    const float* wv_b = (const float*)d_in[8];
    const float* wo_w = (const float*)d_in[9];
    const float* wo_b = (const float*)d_in[10];

    float *gq, *gk, *gv, *ga;
    cudaGetSymbolAddress((void**)&gq, g_q);
    cudaGetSymbolAddress((void**)&gk, g_k);
    cudaGetSymbolAddress((void**)&gv, g_v);
    cudaGetSymbolAddress((void**)&ga, g_att);

    cudaFuncSetAttribute(gemm_mma, cudaFuncAttributeMaxDynamicSharedMemorySize,
                         SMEM_GEMM_BYTES);
    cudaFuncSetAttribute(attn_mma, cudaFuncAttributeMaxDynamicSharedMemorySize,
                         AT_SMEM_BYTES);

    dim3 gemm_grid(D_MODEL / BN, MTOT / BM);   // (8, 32)

    gemm_mma<<<gemm_grid, 256, SMEM_GEMM_BYTES>>>(q, wq_w, wq_b, gq, MTOT, D_MODEL, D_MODEL);
    gemm_mma<<<gemm_grid, 256, SMEM_GEMM_BYTES>>>(k, wk_w, wk_b, gk, MTOT, D_MODEL, D_MODEL);
    gemm_mma<<<gemm_grid, 256, SMEM_GEMM_BYTES>>>(v, wv_w, wv_b, gv, MTOT, D_MODEL, D_MODEL);

    attn_mma<<<dim3(SEQ / 64, BATCH * NHEAD), 128, AT_SMEM_BYTES>>>(gq, gk, gv, ga);

    gemm_mma<<<gemm_grid, 256, SMEM_GEMM_BYTES>>>(ga, wo_w, wo_b, (float*)d_out, MTOT, D_MODEL, D_MODEL);
}

// round 9
// speedup vs baseline: 1.4735x; 1.3502x over previous
#include <cuda_runtime.h>
#include <cstdint>

#define D_MODEL 1024
#define NHEAD   16
#define DK      64
#define BATCH   2
#define SEQ     2048
#define MTOT    (BATCH * SEQ)   // 4096

// Scratch (device globals — no runtime allocation allowed)
__device__ float g_q[MTOT * D_MODEL];
__device__ float g_k[MTOT * D_MODEL];
__device__ float g_v[MTOT * D_MODEL];
__device__ float g_att[MTOT * D_MODEL];

// ============================================================================
// Common helpers
// ============================================================================
__device__ __forceinline__ void cp_async16(uint32_t dst, const void* src) {
    asm volatile("cp.async.ca.shared.global [%0], [%1], 16;"
                 :: "r"(dst), "l"(src) : "memory");
}
__device__ __forceinline__ void cp_commit() {
    asm volatile("cp.async.commit_group;" ::: "memory");
}
__device__ __forceinline__ void cp_wait1() {
    asm volatile("cp.async.wait_group 1;" ::: "memory");
}
__device__ __forceinline__ void cp_wait0() {
    asm volatile("cp.async.wait_group 0;" ::: "memory");
}
__device__ __forceinline__ uint32_t smem_u32(const void* p) {
    uint32_t a;
    asm("{ .reg .u64 t; cvta.to.shared.u64 t, %1; cvt.u32.u64 %0, t; }"
        : "=r"(a) : "l"(p));
    return a;
}
__device__ __forceinline__ uint32_t f2tf32r(float f) {   // round-to-nearest tf32
    uint32_t u;
    asm("cvt.rna.tf32.f32 %0, %1;" : "=r"(u) : "f"(f));
    return u;
}
__device__ __forceinline__ void split_tf32(float v, uint32_t& big, uint32_t& res) {
    uint32_t b = f2tf32r(v);
    big = b;
    res = __float_as_uint(v - __uint_as_float(b));
}
__device__ __forceinline__ void mma_tf32(float& c0, float& c1, float& c2, float& c3,
                                         uint32_t a0, uint32_t a1, uint32_t a2, uint32_t a3,
                                         uint32_t b0, uint32_t b1) {
    asm volatile(
        "mma.sync.aligned.m16n8k8.row.col.f32.tf32.tf32.f32 "
        "{%0,%1,%2,%3}, {%4,%5,%6,%7}, {%8,%9}, {%0,%1,%2,%3};"
        : "+f"(c0), "+f"(c1), "+f"(c2), "+f"(c3)
        : "r"(a0), "r"(a1), "r"(a2), "r"(a3), "r"(b0), "r"(b1));
}

// ============================================================================
// 3xTF32 GEMM:  out[M,N] = X[M,K] @ W[N,K]^T + bias[N]   (fp32-equivalent)
// round_out != 0 -> output values rounded to tf32-rna at store (free rounding
// for downstream tensor-core consumers; makes implicit-RZ reads lossless).
// ============================================================================
#define BM 128
#define BN 128
#define BK 32
#define PITCH 36
#define STAGE_FLOATS (128 * PITCH)
#define SMEM_GEMM_BYTES (4 * STAGE_FLOATS * 4)  // 73728 B

__global__ __launch_bounds__(256) void gemm_mma(
    const float* __restrict__ X, const float* __restrict__ W,
    const float* __restrict__ bias, float* __restrict__ out,
    int M, int N, int K, int round_out)
{
    extern __shared__ __align__(16) float smem[];
    float* As[2] = { smem,                    smem + STAGE_FLOATS };
    float* Bs[2] = { smem + 2 * STAGE_FLOATS, smem + 3 * STAGE_FLOATS };

    const int tid  = threadIdx.x;
    const int wid  = tid >> 5;
    const int lane = tid & 31;
    const int gq   = lane >> 2;
    const int tq   = lane & 3;
    const int warp_m = (wid & 1) * 64;
    const int warp_n = (wid >> 1) * 32;
    const int m0 = blockIdx.y * BM;
    const int n0 = blockIdx.x * BN;

    const int ldr = tid >> 3;
    const int ldc = (tid & 7) * 4;
    const float* Xp = X + (size_t)(m0 + ldr) * K + ldc;
    const float* Wp = W + (size_t)(n0 + ldr) * K + ldc;
    const uint32_t aBase[2] = { smem_u32(As[0]), smem_u32(As[1]) };
    const uint32_t bBase[2] = { smem_u32(Bs[0]), smem_u32(Bs[1]) };
    const uint32_t dstOff = (uint32_t)(ldr * PITCH + ldc) * 4;

    float c[4][4][4];
    #pragma unroll
    for (int i = 0; i < 4; i++)
        #pragma unroll
        for (int j = 0; j < 4; j++) {
            c[i][j][0] = 0.f; c[i][j][1] = 0.f; c[i][j][2] = 0.f; c[i][j][3] = 0.f;
        }

    const int NT = K / BK;

    #pragma unroll
    for (int i = 0; i < 4; i++) {
        uint32_t d = dstOff + (uint32_t)(i * 32 * PITCH * 4);
        cp_async16(aBase[0] + d, Xp + (size_t)i * 32 * K);
        cp_async16(bBase[0] + d, Wp + (size_t)i * 32 * K);
    }
    cp_commit();

    int buf = 0;
    for (int kt = 0; kt < NT; kt++) {
        if (kt + 1 < NT) {
            const float* xs = Xp + (kt + 1) * BK;
            const float* ws = Wp + (kt + 1) * BK;
            const int nb = buf ^ 1;
            #pragma unroll
            for (int i = 0; i < 4; i++) {
                uint32_t d = dstOff + (uint32_t)(i * 32 * PITCH * 4);
                cp_async16(aBase[nb] + d, xs + (size_t)i * 32 * K);
                cp_async16(bBase[nb] + d, ws + (size_t)i * 32 * K);
            }
            cp_commit();
            cp_wait1();
        } else {
            cp_wait0();
        }
        __syncthreads();

        const float* Af = As[buf];
        const float* Bf = Bs[buf];
        #pragma unroll
        for (int s = 0; s < 4; s++) {
            const int k0 = s * 8;
            uint32_t b0b[4], b0r[4], b1b[4], b1r[4];
            #pragma unroll
            for (int nt = 0; nt < 4; nt++) {
                const float* bp = Bf + (warp_n + nt * 8 + gq) * PITCH + k0 + tq;
                split_tf32(bp[0], b0b[nt], b0r[nt]);
                split_tf32(bp[4], b1b[nt], b1r[nt]);
            }
            #pragma unroll
            for (int mt = 0; mt < 4; mt++) {
                const float* ap = Af + (warp_m + mt * 16 + gq) * PITCH + k0 + tq;
                uint32_t ab[4], ar[4];
                split_tf32(ap[0],             ab[0], ar[0]);
                split_tf32(ap[8 * PITCH],     ab[1], ar[1]);
                split_tf32(ap[4],             ab[2], ar[2]);
                split_tf32(ap[8 * PITCH + 4], ab[3], ar[3]);
                #pragma unroll
                for (int nt = 0; nt < 4; nt++) {
                    mma_tf32(c[mt][nt][0], c[mt][nt][1], c[mt][nt][2], c[mt][nt][3],
                             ab[0], ab[1], ab[2], ab[3], b0b[nt], b1b[nt]);
                    mma_tf32(c[mt][nt][0], c[mt][nt][1], c[mt][nt][2], c[mt][nt][3],
                             ab[0], ab[1], ab[2], ab[3], b0r[nt], b1r[nt]);
                    mma_tf32(c[mt][nt][0], c[mt][nt][1], c[mt][nt][2], c[mt][nt][3],
                             ar[0], ar[1], ar[2], ar[3], b0b[nt], b1b[nt]);
                }
            }
        }
        __syncthreads();
        buf ^= 1;
    }

    #pragma unroll
    for (int mt = 0; mt < 4; mt++) {
        const int r0 = m0 + warp_m + mt * 16 + gq;
        #pragma unroll
        for (int nt = 0; nt < 4; nt++) {
            const int col = n0 + warp_n + nt * 8 + tq * 2;
            const float bv0 = bias[col], bv1 = bias[col + 1];
            float2 u, v;
            u.x = c[mt][nt][0] + bv0; u.y = c[mt][nt][1] + bv1;
            v.x = c[mt][nt][2] + bv0; v.y = c[mt][nt][3] + bv1;
            if (round_out) {
                u.x = __uint_as_float(f2tf32r(u.x));
                u.y = __uint_as_float(f2tf32r(u.y));
                v.x = __uint_as_float(f2tf32r(v.x));
                v.y = __uint_as_float(f2tf32r(v.y));
            }
            *(float2*)&out[(size_t)r0 * N + col] = u;
            *(float2*)&out[(size_t)(r0 + 8) * N + col] = v;
        }
    }
}

// ============================================================================
// Flash attention v4 (tf32 mma.sync):
//  Q/K/V scratch are tf32-exact (rounded rna in the projection-GEMM epilogue),
//  so the MMA's implicit RZ truncation is LOSSLESS -> no splits, no in-loop cvt.
//  - S = Q @ K (64 MMAs/tile/warp), P rounded rna with l from rounded P,
//    O += P @ V (64 MMAs). shfl-based C->A conversion (no S smem buffer).
//  CTA = 256 thr = 8 warps, 128 queries/CTA; 2 CTAs/SM (16 warps/SM).
// ============================================================================
#define AT_KP 68
#define AT_VP 72
#define AT_KS0 0
#define AT_KS1 (64 * AT_KP)
#define AT_VS0 (2 * 64 * AT_KP)
#define AT_VS1 (2 * 64 * AT_KP + 64 * AT_VP)
#define AT_SMEM_BYTES ((2 * 64 * AT_KP + 2 * 64 * AT_VP) * 4)   // 71680

__global__ __launch_bounds__(256, 2) void attn_mma(
    const float* __restrict__ Qp, const float* __restrict__ Kp,
    const float* __restrict__ Vp, float* __restrict__ Op)
{
    extern __shared__ __align__(16) float sm[];
    const int tid  = threadIdx.x;
    const int wid  = tid >> 5;          // 0..7
    const int lane = tid & 31;
    const int gq   = lane >> 2;
    const int tq   = lane & 3;
    const int warp_m = wid * 16;        // 0..112
    const int bh = blockIdx.y;
    const int b  = bh >> 4;
    const int h  = bh & 15;
    const int q0 = blockIdx.x * 128;

    const float* Qb = Qp + (size_t)(b * SEQ + q0) * D_MODEL + h * DK;
    const float* Kb = Kp + (size_t)(b * SEQ) * D_MODEL + h * DK;
    const float* Vb = Vp + (size_t)(b * SEQ) * D_MODEL + h * DK;

    // Q fragments: values already tf32-exact; *0.125 (2^-3) keeps them exact.
    uint32_t qa[8][4];
    #pragma unroll
    for (int ks = 0; ks < 8; ks++) {
        const float* qp = Qb + (size_t)(warp_m + gq) * D_MODEL + ks * 8 + tq;
        qa[ks][0] = __float_as_uint(qp[0] * 0.125f);
        qa[ks][1] = __float_as_uint(qp[8 * D_MODEL] * 0.125f);
        qa[ks][2] = __float_as_uint(qp[4] * 0.125f);
        qa[ks][3] = __float_as_uint(qp[8 * D_MODEL + 4] * 0.125f);
    }

    float o[8][4];
    #pragma unroll
    for (int i = 0; i < 8; i++) { o[i][0] = 0.f; o[i][1] = 0.f; o[i][2] = 0.f; o[i][3] = 0.f; }
    const float NEG_INF = __int_as_float(0xff800000);
    float m0 = NEG_INF, m1 = NEG_INF, l0 = 0.f, l1 = 0.f;

    // K/V loaders: 256 threads; row = tid>>2, quad = tid&3 takes 16B chunks
    // at float-col (quad + 4i)*4, i = 0..3.  4 chunks K + 4 chunks V / thread.
    const int ldr = tid >> 2;
    const int ldq = tid & 3;
    const float* Ksrc = Kb + (size_t)ldr * D_MODEL + ldq * 4;
    const float* Vsrc = Vb + (size_t)ldr * D_MODEL + ldq * 4;
    const uint32_t smb = smem_u32(sm);
    const uint32_t kdst0 = smb + (uint32_t)((AT_KS0 + ldr * AT_KP + ldq * 4) * 4);
    const uint32_t kdst1 = smb + (uint32_t)((AT_KS1 + ldr * AT_KP + ldq * 4) * 4);
    const uint32_t vdst0 = smb + (uint32_t)((AT_VS0 + ldr * AT_VP + ldq * 4) * 4);
    const uint32_t vdst1 = smb + (uint32_t)((AT_VS1 + ldr * AT_VP + ldq * 4) * 4);

    #pragma unroll
    for (int i = 0; i < 4; i++) {
        cp_async16(kdst0 + i * 64, Ksrc + i * 16);
        cp_async16(vdst0 + i * 64, Vsrc + i * 16);
    }
    cp_commit();

    // shfl source lanes for C->A fragment conversion
    const int srcl0 = gq * 4 + (tq >> 1);
    const int srcl1 = srcl0 + 2;
    const bool odd = (tq & 1);

    for (int kt = 0; kt < SEQ / 64; kt++) {
        const int buf = kt & 1;
        if (kt + 1 < SEQ / 64) {
            const float* ks2 = Ksrc + (size_t)(kt + 1) * 64 * D_MODEL;
            const float* vs2 = Vsrc + (size_t)(kt + 1) * 64 * D_MODEL;
            const uint32_t kd = buf ? kdst0 : kdst1;
            const uint32_t vd = buf ? vdst0 : vdst1;
            #pragma unroll
            for (int i = 0; i < 4; i++) {
                cp_async16(kd + i * 64, ks2 + i * 16);
                cp_async16(vd + i * 64, vs2 + i * 16);
            }
            cp_commit();
            cp_wait1();
        } else {
            cp_wait0();
        }
        __syncthreads();

        const float* Kst = sm + (buf ? AT_KS1 : AT_KS0);
        const float* Vst = sm + (buf ? AT_VS1 : AT_VS0);

        // ---- S = Q @ K  (both tf32-exact; implicit RZ lossless)
        float s[8][4];
        #pragma unroll
        for (int i = 0; i < 8; i++) { s[i][0] = 0.f; s[i][1] = 0.f; s[i][2] = 0.f; s[i][3] = 0.f; }
        #pragma unroll
        for (int ks = 0; ks < 8; ks++) {
            #pragma unroll
            for (int half = 0; half < 2; half++) {
                uint32_t kb0[4], kb1[4];
                #pragma unroll
                for (int j = 0; j < 4; j++) {
                    const float* kp = Kst + ((half * 4 + j) * 8 + gq) * AT_KP + ks * 8 + tq;
                    kb0[j] = __float_as_uint(kp[0]);
                    kb1[j] = __float_as_uint(kp[4]);
                }
                #pragma unroll
                for (int j = 0; j < 4; j++) {
                    const int nf = half * 4 + j;
                    mma_tf32(s[nf][0], s[nf][1], s[nf][2], s[nf][3],
                             qa[ks][0], qa[ks][1], qa[ks][2], qa[ks][3], kb0[j], kb1[j]);
                }
            }
        }

        // ---- online softmax (row gq -> c0,c1 ; row gq+8 -> c2,c3)
        float mx0 = NEG_INF, mx1 = NEG_INF;
        #pragma unroll
        for (int nf = 0; nf < 8; nf++) {
            mx0 = fmaxf(mx0, fmaxf(s[nf][0], s[nf][1]));
            mx1 = fmaxf(mx1, fmaxf(s[nf][2], s[nf][3]));
        }
        mx0 = fmaxf(mx0, __shfl_xor_sync(0xffffffff, mx0, 1));
        mx0 = fmaxf(mx0, __shfl_xor_sync(0xffffffff, mx0, 2));
        mx1 = fmaxf(mx1, __shfl_xor_sync(0xffffffff, mx1, 1));
        mx1 = fmaxf(mx1, __shfl_xor_sync(0xffffffff, mx1, 2));
        const float m0n = fmaxf(m0, mx0);
        const float m1n = fmaxf(m1, mx1);
        const float fac0 = __expf(m0 - m0n);
        const float fac1 = __expf(m1 - m1n);
        float sum0 = 0.f, sum1 = 0.f;
        // exp, round P to tf32 (rna), accumulate l from the ROUNDED values
        #pragma unroll
        for (int nf = 0; nf < 8; nf++) {
            s[nf][0] = __uint_as_float(f2tf32r(__expf(s[nf][0] - m0n)));
            s[nf][1] = __uint_as_float(f2tf32r(__expf(s[nf][1] - m0n)));
            s[nf][2] = __uint_as_float(f2tf32r(__expf(s[nf][2] - m1n)));
            s[nf][3] = __uint_as_float(f2tf32r(__expf(s[nf][3] - m1n)));
            sum0 += s[nf][0] + s[nf][1];
            sum1 += s[nf][2] + s[nf][3];
        }
        sum0 += __shfl_xor_sync(0xffffffff, sum0, 1);
        sum0 += __shfl_xor_sync(0xffffffff, sum0, 2);
        sum1 += __shfl_xor_sync(0xffffffff, sum1, 1);
        sum1 += __shfl_xor_sync(0xffffffff, sum1, 2);
        m0 = m0n; m1 = m1n;
        l0 = l0 * fac0 + sum0;
        l1 = l1 * fac1 + sum1;

        // ---- rescale O
        #pragma unroll
        for (int nf = 0; nf < 8; nf++) {
            o[nf][0] *= fac0; o[nf][1] *= fac0;
            o[nf][2] *= fac1; o[nf][3] *= fac1;
        }

        // ---- O += P @ V (V tf32-exact) : A-fragments from s[] via shfl
        #pragma unroll
        for (int ks = 0; ks < 8; ks++) {
            const float u0 = __shfl_sync(0xffffffff, s[ks][0], srcl0);
            const float u1 = __shfl_sync(0xffffffff, s[ks][1], srcl0);
            const float u2 = __shfl_sync(0xffffffff, s[ks][2], srcl0);
            const float u3 = __shfl_sync(0xffffffff, s[ks][3], srcl0);
            const float u4 = __shfl_sync(0xffffffff, s[ks][0], srcl1);
            const float u5 = __shfl_sync(0xffffffff, s[ks][1], srcl1);
            const float u6 = __shfl_sync(0xffffffff, s[ks][2], srcl1);
            const float u7 = __shfl_sync(0xffffffff, s[ks][3], srcl1);
            const uint32_t pa0 = __float_as_uint(odd ? u1 : u0);
            const uint32_t pa1 = __float_as_uint(odd ? u3 : u2);
            const uint32_t pa2 = __float_as_uint(odd ? u5 : u4);
            const uint32_t pa3 = __float_as_uint(odd ? u7 : u6);

            #pragma unroll
            for (int half = 0; half < 2; half++) {
                uint32_t vb0[4], vb1[4];
                #pragma unroll
                for (int j = 0; j < 4; j++) {
                    const float* vp = Vst + (ks * 8 + tq) * AT_VP + (half * 4 + j) * 8 + gq;
                    vb0[j] = __float_as_uint(vp[0]);
                    vb1[j] = __float_as_uint(vp[4 * AT_VP]);
                }
                #pragma unroll
                for (int j = 0; j < 4; j++) {
                    const int nf = half * 4 + j;
                    mma_tf32(o[nf][0], o[nf][1], o[nf][2], o[nf][3],
                             pa0, pa1, pa2, pa3, vb0[j], vb1[j]);
                }
            }
        }
        __syncthreads();
    }

    // ---- epilogue: normalize and store
    const float inv0 = 1.f / l0;
    const float inv1 = 1.f / l1;
    float* Ob = Op + (size_t)(b * SEQ + q0 + warp_m + gq) * D_MODEL + h * DK;
    #pragma unroll
    for (int nf = 0; nf < 8; nf++) {
        float2 u, v;
        u.x = o[nf][0] * inv0; u.y = o[nf][1] * inv0;
        v.x = o[nf][2] * inv1; v.y = o[nf][3] * inv1;
        *(float2*)(Ob + nf * 8 + tq * 2) = u;
        *(float2*)(Ob + (size_t)8 * D_MODEL + nf * 8 + tq * 2) = v;
    }
}

// ============================================================================
// Launcher
// ============================================================================
extern "C" void kernel_launch(void* const* d_in, const int* in_sizes, int n_in,
                              void* d_out, int out_size)
{
    const float* q    = (const float*)d_in[0];
    const float* k    = (const float*)d_in[1];
    const float* v    = (const float*)d_in[2];
    const float* wq_w = (const float*)d_in[3];
    const float* wq_b = (const float*)d_in[4];
    const float* wk_w = (const float*)d_in[5];
    const float* wk_b = (const float*)d_in[6];
    const float* wv_w = (const float*)d_in[7];
    const float* wv_b = (const float*)d_in[8];
    const float* wo_w = (const float*)d_in[9];
    const float* wo_b = (const float*)d_in[10];

    float *gq, *gk, *gv, *ga;
    cudaGetSymbolAddress((void**)&gq, g_q);
    cudaGetSymbolAddress((void**)&gk, g_k);
    cudaGetSymbolAddress((void**)&gv, g_v);
    cudaGetSymbolAddress((void**)&ga, g_att);

    cudaFuncSetAttribute(gemm_mma, cudaFuncAttributeMaxDynamicSharedMemorySize,
                         SMEM_GEMM_BYTES);
    cudaFuncSetAttribute(attn_mma, cudaFuncAttributeMaxDynamicSharedMemorySize,
                         AT_SMEM_BYTES);

    dim3 gemm_grid(D_MODEL / BN, MTOT / BM);   // (8, 32)

    // Q/K/V projections: outputs rounded to tf32 (rna) in the epilogue.
    gemm_mma<<<gemm_grid, 256, SMEM_GEMM_BYTES>>>(q, wq_w, wq_b, gq, MTOT, D_MODEL, D_MODEL, 1);
    gemm_mma<<<gemm_grid, 256, SMEM_GEMM_BYTES>>>(k, wk_w, wk_b, gk, MTOT, D_MODEL, D_MODEL, 1);
    gemm_mma<<<gemm_grid, 256, SMEM_GEMM_BYTES>>>(v, wv_w, wv_b, gv, MTOT, D_MODEL, D_MODEL, 1);

    attn_mma<<<dim3(SEQ / 128, BATCH * NHEAD), 256, AT_SMEM_BYTES>>>(gq, gk, gv, ga);

    // Output projection: full precision store.
    gemm_mma<<<gemm_grid, 256, SMEM_GEMM_BYTES>>>(ga, wo_w, wo_b, (float*)d_out, MTOT, D_MODEL, D_MODEL, 0);
}

// round 12
// speedup vs baseline: 1.7633x; 1.1966x over previous
#include <cuda_runtime.h>
#include <cstdint>

#define D_MODEL 1024
#define NHEAD   16
#define DK      64
#define BATCH   2
#define SEQ     2048
#define MTOT    (BATCH * SEQ)   // 4096

// Scratch (device globals — no runtime allocation allowed)
__device__ float g_q[MTOT * D_MODEL];
__device__ float g_k[MTOT * D_MODEL];
__device__ float g_v[MTOT * D_MODEL];
__device__ float g_att[MTOT * D_MODEL];

// ============================================================================
// Common helpers
// ============================================================================
__device__ __forceinline__ void cp_async16(uint32_t dst, const void* src) {
    asm volatile("cp.async.ca.shared.global [%0], [%1], 16;"
                 :: "r"(dst), "l"(src) : "memory");
}
__device__ __forceinline__ void cp_commit() {
    asm volatile("cp.async.commit_group;" ::: "memory");
}
__device__ __forceinline__ void cp_wait1() {
    asm volatile("cp.async.wait_group 1;" ::: "memory");
}
__device__ __forceinline__ void cp_wait0() {
    asm volatile("cp.async.wait_group 0;" ::: "memory");
}
__device__ __forceinline__ uint32_t smem_u32(const void* p) {
    uint32_t a;
    asm("{ .reg .u64 t; cvta.to.shared.u64 t, %1; cvt.u32.u64 %0, t; }"
        : "=r"(a) : "l"(p));
    return a;
}
__device__ __forceinline__ uint32_t f2tf32r(float f) {   // round-to-nearest tf32
    uint32_t u;
    asm("cvt.rna.tf32.f32 %0, %1;" : "=r"(u) : "f"(f));
    return u;
}
__device__ __forceinline__ void split_tf32(float v, uint32_t& big, uint32_t& res) {
    uint32_t b = f2tf32r(v);
    big = b;
    res = __float_as_uint(v - __uint_as_float(b));
}
__device__ __forceinline__ void mma_tf32(float& c0, float& c1, float& c2, float& c3,
                                         uint32_t a0, uint32_t a1, uint32_t a2, uint32_t a3,
                                         uint32_t b0, uint32_t b1) {
    asm volatile(
        "mma.sync.aligned.m16n8k8.row.col.f32.tf32.tf32.f32 "
        "{%0,%1,%2,%3}, {%4,%5,%6,%7}, {%8,%9}, {%0,%1,%2,%3};"
        : "+f"(c0), "+f"(c1), "+f"(c2), "+f"(c3)
        : "r"(a0), "r"(a1), "r"(a2), "r"(a3), "r"(b0), "r"(b1));
}

// ============================================================================
// GEMM:  out[M,N] = rna(X)[M,K] @ W[N,K]^T + bias[N]
// A rounded tf32-rna at fragment load (single error source ~2e-4);
// W kept EXACT via 2-term split (Wb + Wr) -> W truncation cancels.
// 128 MMAs / k-tile / warp (was 192 with the 3xTF32 scheme).
// round_out != 0 -> output rounded tf32-rna at store (for tensor-core readers).
// ============================================================================
#define BM 128
#define BN 128
#define BK 32
#define PITCH 36
#define STAGE_FLOATS (128 * PITCH)
#define SMEM_GEMM_BYTES (4 * STAGE_FLOATS * 4)  // 73728 B

__global__ __launch_bounds__(256) void gemm_mma(
    const float* __restrict__ X, const float* __restrict__ W,
    const float* __restrict__ bias, float* __restrict__ out,
    int M, int N, int K, int round_out)
{
    extern __shared__ __align__(16) float smem[];
    float* As[2] = { smem,                    smem + STAGE_FLOATS };
    float* Bs[2] = { smem + 2 * STAGE_FLOATS, smem + 3 * STAGE_FLOATS };

    const int tid  = threadIdx.x;
    const int wid  = tid >> 5;
    const int lane = tid & 31;
    const int gq   = lane >> 2;
    const int tq   = lane & 3;
    const int warp_m = (wid & 1) * 64;
    const int warp_n = (wid >> 1) * 32;
    const int m0 = blockIdx.y * BM;
    const int n0 = blockIdx.x * BN;

    const int ldr = tid >> 3;
    const int ldc = (tid & 7) * 4;
    const float* Xp = X + (size_t)(m0 + ldr) * K + ldc;
    const float* Wp = W + (size_t)(n0 + ldr) * K + ldc;
    const uint32_t aBase[2] = { smem_u32(As[0]), smem_u32(As[1]) };
    const uint32_t bBase[2] = { smem_u32(Bs[0]), smem_u32(Bs[1]) };
    const uint32_t dstOff = (uint32_t)(ldr * PITCH + ldc) * 4;

    float c[4][4][4];
    #pragma unroll
    for (int i = 0; i < 4; i++)
        #pragma unroll
        for (int j = 0; j < 4; j++) {
            c[i][j][0] = 0.f; c[i][j][1] = 0.f; c[i][j][2] = 0.f; c[i][j][3] = 0.f;
        }

    const int NT = K / BK;

    #pragma unroll
    for (int i = 0; i < 4; i++) {
        uint32_t d = dstOff + (uint32_t)(i * 32 * PITCH * 4);
        cp_async16(aBase[0] + d, Xp + (size_t)i * 32 * K);
        cp_async16(bBase[0] + d, Wp + (size_t)i * 32 * K);
    }
    cp_commit();

    int buf = 0;
    for (int kt = 0; kt < NT; kt++) {
        if (kt + 1 < NT) {
            const float* xs = Xp + (kt + 1) * BK;
            const float* ws = Wp + (kt + 1) * BK;
            const int nb = buf ^ 1;
            #pragma unroll
            for (int i = 0; i < 4; i++) {
                uint32_t d = dstOff + (uint32_t)(i * 32 * PITCH * 4);
                cp_async16(aBase[nb] + d, xs + (size_t)i * 32 * K);
                cp_async16(bBase[nb] + d, ws + (size_t)i * 32 * K);
            }
            cp_commit();
            cp_wait1();
        } else {
            cp_wait0();
        }
        __syncthreads();

        const float* Af = As[buf];
        const float* Bf = Bs[buf];
        #pragma unroll
        for (int s = 0; s < 4; s++) {
            const int k0 = s * 8;
            uint32_t b0b[4], b0r[4], b1b[4], b1r[4];
            #pragma unroll
            for (int nt = 0; nt < 4; nt++) {
                const float* bp = Bf + (warp_n + nt * 8 + gq) * PITCH + k0 + tq;
                split_tf32(bp[0], b0b[nt], b0r[nt]);
                split_tf32(bp[4], b1b[nt], b1r[nt]);
            }
            #pragma unroll
            for (int mt = 0; mt < 4; mt++) {
                const float* ap = Af + (warp_m + mt * 16 + gq) * PITCH + k0 + tq;
                const uint32_t a0 = f2tf32r(ap[0]);
                const uint32_t a1 = f2tf32r(ap[8 * PITCH]);
                const uint32_t a2 = f2tf32r(ap[4]);
                const uint32_t a3 = f2tf32r(ap[8 * PITCH + 4]);
                #pragma unroll
                for (int nt = 0; nt < 4; nt++) {
                    mma_tf32(c[mt][nt][0], c[mt][nt][1], c[mt][nt][2], c[mt][nt][3],
                             a0, a1, a2, a3, b0b[nt], b1b[nt]);
                    mma_tf32(c[mt][nt][0], c[mt][nt][1], c[mt][nt][2], c[mt][nt][3],
                             a0, a1, a2, a3, b0r[nt], b1r[nt]);
                }
            }
        }
        __syncthreads();
        buf ^= 1;
    }

    #pragma unroll
    for (int mt = 0; mt < 4; mt++) {
        const int r0 = m0 + warp_m + mt * 16 + gq;
        #pragma unroll
        for (int nt = 0; nt < 4; nt++) {
            const int col = n0 + warp_n + nt * 8 + tq * 2;
            const float bv0 = bias[col], bv1 = bias[col + 1];
            float2 u, v;
            u.x = c[mt][nt][0] + bv0; u.y = c[mt][nt][1] + bv1;
            v.x = c[mt][nt][2] + bv0; v.y = c[mt][nt][3] + bv1;
            if (round_out) {
                u.x = __uint_as_float(f2tf32r(u.x));
                u.y = __uint_as_float(f2tf32r(u.y));
                v.x = __uint_as_float(f2tf32r(v.x));
                v.y = __uint_as_float(f2tf32r(v.y));
            }
            *(float2*)&out[(size_t)r0 * N + col] = u;
            *(float2*)&out[(size_t)(r0 + 8) * N + col] = v;
        }
    }
}

// ============================================================================
// Flash attention v4 (tf32 mma.sync):
//  Q/K/V scratch are tf32-exact (rounded rna in the projection-GEMM epilogue),
//  so the MMA's implicit RZ truncation is LOSSLESS -> no splits, no in-loop cvt.
//  - S = Q @ K (64 MMAs/tile/warp), P rounded rna with l from rounded P,
//    O += P @ V (64 MMAs). shfl-based C->A conversion (no S smem buffer).
//  Output rounded tf32-rna at store (read losslessly by the out-projection).
//  CTA = 256 thr = 8 warps, 128 queries/CTA; 2 CTAs/SM (16 warps/SM).
// ============================================================================
#define AT_KP 68
#define AT_VP 72
#define AT_KS0 0
#define AT_KS1 (64 * AT_KP)
#define AT_VS0 (2 * 64 * AT_KP)
#define AT_VS1 (2 * 64 * AT_KP + 64 * AT_VP)
#define AT_SMEM_BYTES ((2 * 64 * AT_KP + 2 * 64 * AT_VP) * 4)   // 71680

__global__ __launch_bounds__(256, 2) void attn_mma(
    const float* __restrict__ Qp, const float* __restrict__ Kp,
    const float* __restrict__ Vp, float* __restrict__ Op)
{
    extern __shared__ __align__(16) float sm[];
    const int tid  = threadIdx.x;
    const int wid  = tid >> 5;          // 0..7
    const int lane = tid & 31;
    const int gq   = lane >> 2;
    const int tq   = lane & 3;
    const int warp_m = wid * 16;        // 0..112
    const int bh = blockIdx.y;
    const int b  = bh >> 4;
    const int h  = bh & 15;
    const int q0 = blockIdx.x * 128;

    const float* Qb = Qp + (size_t)(b * SEQ + q0) * D_MODEL + h * DK;
    const float* Kb = Kp + (size_t)(b * SEQ) * D_MODEL + h * DK;
    const float* Vb = Vp + (size_t)(b * SEQ) * D_MODEL + h * DK;

    // Q fragments: values already tf32-exact; *0.125 (2^-3) keeps them exact.
    uint32_t qa[8][4];
    #pragma unroll
    for (int ks = 0; ks < 8; ks++) {
        const float* qp = Qb + (size_t)(warp_m + gq) * D_MODEL + ks * 8 + tq;
        qa[ks][0] = __float_as_uint(qp[0] * 0.125f);
        qa[ks][1] = __float_as_uint(qp[8 * D_MODEL] * 0.125f);
        qa[ks][2] = __float_as_uint(qp[4] * 0.125f);
        qa[ks][3] = __float_as_uint(qp[8 * D_MODEL + 4] * 0.125f);
    }

    float o[8][4];
    #pragma unroll
    for (int i = 0; i < 8; i++) { o[i][0] = 0.f; o[i][1] = 0.f; o[i][2] = 0.f; o[i][3] = 0.f; }
    const float NEG_INF = __int_as_float(0xff800000);
    float m0 = NEG_INF, m1 = NEG_INF, l0 = 0.f, l1 = 0.f;

    // K/V loaders: 256 threads; row = tid>>2, quad = tid&3 takes 16B chunks
    // at float-col (quad + 4i)*4, i = 0..3.  4 chunks K + 4 chunks V / thread.
    const int ldr = tid >> 2;
    const int ldq = tid & 3;
    const float* Ksrc = Kb + (size_t)ldr * D_MODEL + ldq * 4;
    const float* Vsrc = Vb + (size_t)ldr * D_MODEL + ldq * 4;
    const uint32_t smb = smem_u32(sm);
    const uint32_t kdst0 = smb + (uint32_t)((AT_KS0 + ldr * AT_KP + ldq * 4) * 4);
    const uint32_t kdst1 = smb + (uint32_t)((AT_KS1 + ldr * AT_KP + ldq * 4) * 4);
    const uint32_t vdst0 = smb + (uint32_t)((AT_VS0 + ldr * AT_VP + ldq * 4) * 4);
    const uint32_t vdst1 = smb + (uint32_t)((AT_VS1 + ldr * AT_VP + ldq * 4) * 4);

    #pragma unroll
    for (int i = 0; i < 4; i++) {
        cp_async16(kdst0 + i * 64, Ksrc + i * 16);
        cp_async16(vdst0 + i * 64, Vsrc + i * 16);
    }
    cp_commit();

    // shfl source lanes for C->A fragment conversion
    const int srcl0 = gq * 4 + (tq >> 1);
    const int srcl1 = srcl0 + 2;
    const bool odd = (tq & 1);

    for (int kt = 0; kt < SEQ / 64; kt++) {
        const int buf = kt & 1;
        if (kt + 1 < SEQ / 64) {
            const float* ks2 = Ksrc + (size_t)(kt + 1) * 64 * D_MODEL;
            const float* vs2 = Vsrc + (size_t)(kt + 1) * 64 * D_MODEL;
            const uint32_t kd = buf ? kdst0 : kdst1;
            const uint32_t vd = buf ? vdst0 : vdst1;
            #pragma unroll
            for (int i = 0; i < 4; i++) {
                cp_async16(kd + i * 64, ks2 + i * 16);
                cp_async16(vd + i * 64, vs2 + i * 16);
            }
            cp_commit();
            cp_wait1();
        } else {
            cp_wait0();
        }
        __syncthreads();

        const float* Kst = sm + (buf ? AT_KS1 : AT_KS0);
        const float* Vst = sm + (buf ? AT_VS1 : AT_VS0);

        // ---- S = Q @ K  (both tf32-exact; implicit RZ lossless)
        float s[8][4];
        #pragma unroll
        for (int i = 0; i < 8; i++) { s[i][0] = 0.f; s[i][1] = 0.f; s[i][2] = 0.f; s[i][3] = 0.f; }
        #pragma unroll
        for (int ks = 0; ks < 8; ks++) {
            #pragma unroll
            for (int half = 0; half < 2; half++) {
                uint32_t kb0[4], kb1[4];
                #pragma unroll
                for (int j = 0; j < 4; j++) {
                    const float* kp = Kst + ((half * 4 + j) * 8 + gq) * AT_KP + ks * 8 + tq;
                    kb0[j] = __float_as_uint(kp[0]);
                    kb1[j] = __float_as_uint(kp[4]);
                }
                #pragma unroll
                for (int j = 0; j < 4; j++) {
                    const int nf = half * 4 + j;
                    mma_tf32(s[nf][0], s[nf][1], s[nf][2], s[nf][3],
                             qa[ks][0], qa[ks][1], qa[ks][2], qa[ks][3], kb0[j], kb1[j]);
                }
            }
        }

        // ---- online softmax (row gq -> c0,c1 ; row gq+8 -> c2,c3)
        float mx0 = NEG_INF, mx1 = NEG_INF;
        #pragma unroll
        for (int nf = 0; nf < 8; nf++) {
            mx0 = fmaxf(mx0, fmaxf(s[nf][0], s[nf][1]));
            mx1 = fmaxf(mx1, fmaxf(s[nf][2], s[nf][3]));
        }
        mx0 = fmaxf(mx0, __shfl_xor_sync(0xffffffff, mx0, 1));
        mx0 = fmaxf(mx0, __shfl_xor_sync(0xffffffff, mx0, 2));
        mx1 = fmaxf(mx1, __shfl_xor_sync(0xffffffff, mx1, 1));
        mx1 = fmaxf(mx1, __shfl_xor_sync(0xffffffff, mx1, 2));
        const float m0n = fmaxf(m0, mx0);
        const float m1n = fmaxf(m1, mx1);
        const float fac0 = __expf(m0 - m0n);
        const float fac1 = __expf(m1 - m1n);
        float sum0 = 0.f, sum1 = 0.f;
        // exp, round P to tf32 (rna), accumulate l from the ROUNDED values
        #pragma unroll
        for (int nf = 0; nf < 8; nf++) {
            s[nf][0] = __uint_as_float(f2tf32r(__expf(s[nf][0] - m0n)));
            s[nf][1] = __uint_as_float(f2tf32r(__expf(s[nf][1] - m0n)));
            s[nf][2] = __uint_as_float(f2tf32r(__expf(s[nf][2] - m1n)));
            s[nf][3] = __uint_as_float(f2tf32r(__expf(s[nf][3] - m1n)));
            sum0 += s[nf][0] + s[nf][1];
            sum1 += s[nf][2] + s[nf][3];
        }
        sum0 += __shfl_xor_sync(0xffffffff, sum0, 1);
        sum0 += __shfl_xor_sync(0xffffffff, sum0, 2);
        sum1 += __shfl_xor_sync(0xffffffff, sum1, 1);
        sum1 += __shfl_xor_sync(0xffffffff, sum1, 2);
        m0 = m0n; m1 = m1n;
        l0 = l0 * fac0 + sum0;
        l1 = l1 * fac1 + sum1;

        // ---- rescale O
        #pragma unroll
        for (int nf = 0; nf < 8; nf++) {
            o[nf][0] *= fac0; o[nf][1] *= fac0;
            o[nf][2] *= fac1; o[nf][3] *= fac1;
        }

        // ---- O += P @ V (V tf32-exact) : A-fragments from s[] via shfl
        #pragma unroll
        for (int ks = 0; ks < 8; ks++) {
            const float u0 = __shfl_sync(0xffffffff, s[ks][0], srcl0);
            const float u1 = __shfl_sync(0xffffffff, s[ks][1], srcl0);
            const float u2 = __shfl_sync(0xffffffff, s[ks][2], srcl0);
            const float u3 = __shfl_sync(0xffffffff, s[ks][3], srcl0);
            const float u4 = __shfl_sync(0xffffffff, s[ks][0], srcl1);
            const float u5 = __shfl_sync(0xffffffff, s[ks][1], srcl1);
            const float u6 = __shfl_sync(0xffffffff, s[ks][2], srcl1);
            const float u7 = __shfl_sync(0xffffffff, s[ks][3], srcl1);
            const uint32_t pa0 = __float_as_uint(odd ? u1 : u0);
            const uint32_t pa1 = __float_as_uint(odd ? u3 : u2);
            const uint32_t pa2 = __float_as_uint(odd ? u5 : u4);
            const uint32_t pa3 = __float_as_uint(odd ? u7 : u6);

            #pragma unroll
            for (int half = 0; half < 2; half++) {
                uint32_t vb0[4], vb1[4];
                #pragma unroll
                for (int j = 0; j < 4; j++) {
                    const float* vp = Vst + (ks * 8 + tq) * AT_VP + (half * 4 + j) * 8 + gq;
                    vb0[j] = __float_as_uint(vp[0]);
                    vb1[j] = __float_as_uint(vp[4 * AT_VP]);
                }
                #pragma unroll
                for (int j = 0; j < 4; j++) {
                    const int nf = half * 4 + j;
                    mma_tf32(o[nf][0], o[nf][1], o[nf][2], o[nf][3],
                             pa0, pa1, pa2, pa3, vb0[j], vb1[j]);
                }
            }
        }
        __syncthreads();
    }

    // ---- epilogue: normalize, round to tf32 (lossless read downstream), store
    const float inv0 = 1.f / l0;
    const float inv1 = 1.f / l1;
    float* Ob = Op + (size_t)(b * SEQ + q0 + warp_m + gq) * D_MODEL + h * DK;
    #pragma unroll
    for (int nf = 0; nf < 8; nf++) {
        float2 u, v;
        u.x = __uint_as_float(f2tf32r(o[nf][0] * inv0));
        u.y = __uint_as_float(f2tf32r(o[nf][1] * inv0));
        v.x = __uint_as_float(f2tf32r(o[nf][2] * inv1));
        v.y = __uint_as_float(f2tf32r(o[nf][3] * inv1));
        *(float2*)(Ob + nf * 8 + tq * 2) = u;
        *(float2*)(Ob + (size_t)8 * D_MODEL + nf * 8 + tq * 2) = v;
    }
}

// ============================================================================
// Launcher
// ============================================================================
extern "C" void kernel_launch(void* const* d_in, const int* in_sizes, int n_in,
                              void* d_out, int out_size)
{
    const float* q    = (const float*)d_in[0];
    const float* k    = (const float*)d_in[1];
    const float* v    = (const float*)d_in[2];
    const float* wq_w = (const float*)d_in[3];
    const float* wq_b = (const float*)d_in[4];
    const float* wk_w = (const float*)d_in[5];
    const float* wk_b = (const float*)d_in[6];
    const float* wv_w = (const float*)d_in[7];
    const float* wv_b = (const float*)d_in[8];
    const float* wo_w = (const float*)d_in[9];
    const float* wo_b = (const float*)d_in[10];

    float *gq, *gk, *gv, *ga;
    cudaGetSymbolAddress((void**)&gq, g_q);
    cudaGetSymbolAddress((void**)&gk, g_k);
    cudaGetSymbolAddress((void**)&gv, g_v);
    cudaGetSymbolAddress((void**)&ga, g_att);

    cudaFuncSetAttribute(gemm_mma, cudaFuncAttributeMaxDynamicSharedMemorySize,
                         SMEM_GEMM_BYTES);
    cudaFuncSetAttribute(attn_mma, cudaFuncAttributeMaxDynamicSharedMemorySize,
                         AT_SMEM_BYTES);

    dim3 gemm_grid(D_MODEL / BN, MTOT / BM);   // (8, 32)

    // Q/K/V projections: outputs rounded to tf32 (rna) in the epilogue.
    gemm_mma<<<gemm_grid, 256, SMEM_GEMM_BYTES>>>(q, wq_w, wq_b, gq, MTOT, D_MODEL, D_MODEL, 1);
    gemm_mma<<<gemm_grid, 256, SMEM_GEMM_BYTES>>>(k, wk_w, wk_b, gk, MTOT, D_MODEL, D_MODEL, 1);
    gemm_mma<<<gemm_grid, 256, SMEM_GEMM_BYTES>>>(v, wv_w, wv_b, gv, MTOT, D_MODEL, D_MODEL, 1);

    attn_mma<<<dim3(SEQ / 128, BATCH * NHEAD), 256, AT_SMEM_BYTES>>>(gq, gk, gv, ga);

    // Output projection: full precision store (attn output already tf32-exact).
    gemm_mma<<<gemm_grid, 256, SMEM_GEMM_BYTES>>>(ga, wo_w, wo_b, (float*)d_out, MTOT, D_MODEL, D_MODEL, 0);
}

// round 13
// speedup vs baseline: 2.2590x; 1.2811x over previous
#include <cuda_runtime.h>
#include <cstdint>

#define D_MODEL 1024
#define NHEAD   16
#define DK      64
#define BATCH   2
#define SEQ     2048
#define MTOT    (BATCH * SEQ)   // 4096

// Scratch (device globals — no runtime allocation allowed)
__device__ float g_q[MTOT * D_MODEL];
__device__ float g_k[MTOT * D_MODEL];
__device__ float g_v[MTOT * D_MODEL];
__device__ float g_att[MTOT * D_MODEL];
// tf32-rounded weights (filled by round_w each launch)
__device__ float g_wq[D_MODEL * D_MODEL];
__device__ float g_wk[D_MODEL * D_MODEL];
__device__ float g_wv[D_MODEL * D_MODEL];
__device__ float g_wo[D_MODEL * D_MODEL];

// ============================================================================
// Common helpers
// ============================================================================
__device__ __forceinline__ void cp_async16(uint32_t dst, const void* src) {
    asm volatile("cp.async.ca.shared.global [%0], [%1], 16;"
                 :: "r"(dst), "l"(src) : "memory");
}
__device__ __forceinline__ void cp_commit() {
    asm volatile("cp.async.commit_group;" ::: "memory");
}
__device__ __forceinline__ void cp_wait1() {
    asm volatile("cp.async.wait_group 1;" ::: "memory");
}
__device__ __forceinline__ void cp_wait0() {
    asm volatile("cp.async.wait_group 0;" ::: "memory");
}
__device__ __forceinline__ uint32_t smem_u32(const void* p) {
    uint32_t a;
    asm("{ .reg .u64 t; cvta.to.shared.u64 t, %1; cvt.u32.u64 %0, t; }"
        : "=r"(a) : "l"(p));
    return a;
}
__device__ __forceinline__ uint32_t f2tf32r(float f) {   // round-to-nearest tf32
    uint32_t u;
    asm("cvt.rna.tf32.f32 %0, %1;" : "=r"(u) : "f"(f));
    return u;
}
__device__ __forceinline__ void mma_tf32(float& c0, float& c1, float& c2, float& c3,
                                         uint32_t a0, uint32_t a1, uint32_t a2, uint32_t a3,
                                         uint32_t b0, uint32_t b1) {
    asm volatile(
        "mma.sync.aligned.m16n8k8.row.col.f32.tf32.tf32.f32 "
        "{%0,%1,%2,%3}, {%4,%5,%6,%7}, {%8,%9}, {%0,%1,%2,%3};"
        : "+f"(c0), "+f"(c1), "+f"(c2), "+f"(c3)
        : "r"(a0), "r"(a1), "r"(a2), "r"(a3), "r"(b0), "r"(b1));
}

// ============================================================================
// Weight pre-rounding: out[i] = rna_tf32(in[i]).  1M elements per weight.
// ============================================================================
__global__ __launch_bounds__(256) void round_w(const float* __restrict__ in,
                                               float* __restrict__ out) {
    const int i = (blockIdx.x * 256 + threadIdx.x) * 4;
    float4 v = *(const float4*)(in + i);
    v.x = __uint_as_float(f2tf32r(v.x));
    v.y = __uint_as_float(f2tf32r(v.y));
    v.z = __uint_as_float(f2tf32r(v.z));
    v.w = __uint_as_float(f2tf32r(v.w));
    *(float4*)(out + i) = v;
}

// ============================================================================
// GEMM:  out[M,N] = rna(X)[M,K] @ W[N,K]^T + bias[N]
// W must be tf32-exact (pre-rounded) -> implicit RZ lossless, no split.
// A rounded tf32-rna at fragment load. 64 MMAs / k-tile / warp.
// round_out != 0 -> output rounded tf32-rna at store (for tensor-core readers).
// ============================================================================
#define BM 128
#define BN 128
#define BK 32
#define PITCH 36
#define STAGE_FLOATS (128 * PITCH)
#define SMEM_GEMM_BYTES (4 * STAGE_FLOATS * 4)  // 73728 B

__global__ __launch_bounds__(256) void gemm_mma(
    const float* __restrict__ X, const float* __restrict__ W,
    const float* __restrict__ bias, float* __restrict__ out,
    int M, int N, int K, int round_out)
{
    extern __shared__ __align__(16) float smem[];
    float* As[2] = { smem,                    smem + STAGE_FLOATS };
    float* Bs[2] = { smem + 2 * STAGE_FLOATS, smem + 3 * STAGE_FLOATS };

    const int tid  = threadIdx.x;
    const int wid  = tid >> 5;
    const int lane = tid & 31;
    const int gq   = lane >> 2;
    const int tq   = lane & 3;
    const int warp_m = (wid & 1) * 64;
    const int warp_n = (wid >> 1) * 32;
    const int m0 = blockIdx.y * BM;
    const int n0 = blockIdx.x * BN;

    const int ldr = tid >> 3;
    const int ldc = (tid & 7) * 4;
    const float* Xp = X + (size_t)(m0 + ldr) * K + ldc;
    const float* Wp = W + (size_t)(n0 + ldr) * K + ldc;
    const uint32_t aBase[2] = { smem_u32(As[0]), smem_u32(As[1]) };
    const uint32_t bBase[2] = { smem_u32(Bs[0]), smem_u32(Bs[1]) };
    const uint32_t dstOff = (uint32_t)(ldr * PITCH + ldc) * 4;

    float c[4][4][4];
    #pragma unroll
    for (int i = 0; i < 4; i++)
        #pragma unroll
        for (int j = 0; j < 4; j++) {
            c[i][j][0] = 0.f; c[i][j][1] = 0.f; c[i][j][2] = 0.f; c[i][j][3] = 0.f;
        }

    const int NT = K / BK;

    #pragma unroll
    for (int i = 0; i < 4; i++) {
        uint32_t d = dstOff + (uint32_t)(i * 32 * PITCH * 4);
        cp_async16(aBase[0] + d, Xp + (size_t)i * 32 * K);
        cp_async16(bBase[0] + d, Wp + (size_t)i * 32 * K);
    }
    cp_commit();

    int buf = 0;
    for (int kt = 0; kt < NT; kt++) {
        if (kt + 1 < NT) {
            const float* xs = Xp + (kt + 1) * BK;
            const float* ws = Wp + (kt + 1) * BK;
            const int nb = buf ^ 1;
            #pragma unroll
            for (int i = 0; i < 4; i++) {
                uint32_t d = dstOff + (uint32_t)(i * 32 * PITCH * 4);
                cp_async16(aBase[nb] + d, xs + (size_t)i * 32 * K);
                cp_async16(bBase[nb] + d, ws + (size_t)i * 32 * K);
            }
            cp_commit();
            cp_wait1();
        } else {
            cp_wait0();
        }
        __syncthreads();

        const float* Af = As[buf];
        const float* Bf = Bs[buf];
        #pragma unroll
        for (int s = 0; s < 4; s++) {
            const int k0 = s * 8;
            uint32_t b0[4], b1[4];
            #pragma unroll
            for (int nt = 0; nt < 4; nt++) {
                const float* bp = Bf + (warp_n + nt * 8 + gq) * PITCH + k0 + tq;
                b0[nt] = __float_as_uint(bp[0]);
                b1[nt] = __float_as_uint(bp[4]);
            }
            #pragma unroll
            for (int mt = 0; mt < 4; mt++) {
                const float* ap = Af + (warp_m + mt * 16 + gq) * PITCH + k0 + tq;
                const uint32_t a0 = f2tf32r(ap[0]);
                const uint32_t a1 = f2tf32r(ap[8 * PITCH]);
                const uint32_t a2 = f2tf32r(ap[4]);
                const uint32_t a3 = f2tf32r(ap[8 * PITCH + 4]);
                #pragma unroll
                for (int nt = 0; nt < 4; nt++)
                    mma_tf32(c[mt][nt][0], c[mt][nt][1], c[mt][nt][2], c[mt][nt][3],
                             a0, a1, a2, a3, b0[nt], b1[nt]);
            }
        }
        __syncthreads();
        buf ^= 1;
    }

    #pragma unroll
    for (int mt = 0; mt < 4; mt++) {
        const int r0 = m0 + warp_m + mt * 16 + gq;
        #pragma unroll
        for (int nt = 0; nt < 4; nt++) {
            const int col = n0 + warp_n + nt * 8 + tq * 2;
            const float bv0 = bias[col], bv1 = bias[col + 1];
            float2 u, v;
            u.x = c[mt][nt][0] + bv0; u.y = c[mt][nt][1] + bv1;
            v.x = c[mt][nt][2] + bv0; v.y = c[mt][nt][3] + bv1;
            if (round_out) {
                u.x = __uint_as_float(f2tf32r(u.x));
                u.y = __uint_as_float(f2tf32r(u.y));
                v.x = __uint_as_float(f2tf32r(v.x));
                v.y = __uint_as_float(f2tf32r(v.y));
            }
            *(float2*)&out[(size_t)r0 * N + col] = u;
            *(float2*)&out[(size_t)(r0 + 8) * N + col] = v;
        }
    }
}

// ============================================================================
// Flash attention v4 (tf32 mma.sync):
//  Q/K/V scratch are tf32-exact (rounded rna in the projection-GEMM epilogue),
//  so the MMA's implicit RZ truncation is LOSSLESS -> no splits, no in-loop cvt.
//  - S = Q @ K (64 MMAs/tile/warp), P rounded rna with l from rounded P,
//    O += P @ V (64 MMAs). shfl-based C->A conversion (no S smem buffer).
//  Output rounded tf32-rna at store (read losslessly by the out-projection).
//  CTA = 256 thr = 8 warps, 128 queries/CTA; 2 CTAs/SM (16 warps/SM).
// ============================================================================
#define AT_KP 68
#define AT_VP 72
#define AT_KS0 0
#define AT_KS1 (64 * AT_KP)
#define AT_VS0 (2 * 64 * AT_KP)
#define AT_VS1 (2 * 64 * AT_KP + 64 * AT_VP)
#define AT_SMEM_BYTES ((2 * 64 * AT_KP + 2 * 64 * AT_VP) * 4)   // 71680

__global__ __launch_bounds__(256, 2) void attn_mma(
    const float* __restrict__ Qp, const float* __restrict__ Kp,
    const float* __restrict__ Vp, float* __restrict__ Op)
{
    extern __shared__ __align__(16) float sm[];
    const int tid  = threadIdx.x;
    const int wid  = tid >> 5;          // 0..7
    const int lane = tid & 31;
    const int gq   = lane >> 2;
    const int tq   = lane & 3;
    const int warp_m = wid * 16;        // 0..112
    const int bh = blockIdx.y;
    const int b  = bh >> 4;
    const int h  = bh & 15;
    const int q0 = blockIdx.x * 128;

    const float* Qb = Qp + (size_t)(b * SEQ + q0) * D_MODEL + h * DK;
    const float* Kb = Kp + (size_t)(b * SEQ) * D_MODEL + h * DK;
    const float* Vb = Vp + (size_t)(b * SEQ) * D_MODEL + h * DK;

    // Q fragments: values already tf32-exact; *0.125 (2^-3) keeps them exact.
    uint32_t qa[8][4];
    #pragma unroll
    for (int ks = 0; ks < 8; ks++) {
        const float* qp = Qb + (size_t)(warp_m + gq) * D_MODEL + ks * 8 + tq;
        qa[ks][0] = __float_as_uint(qp[0] * 0.125f);
        qa[ks][1] = __float_as_uint(qp[8 * D_MODEL] * 0.125f);
        qa[ks][2] = __float_as_uint(qp[4] * 0.125f);
        qa[ks][3] = __float_as_uint(qp[8 * D_MODEL + 4] * 0.125f);
    }

    float o[8][4];
    #pragma unroll
    for (int i = 0; i < 8; i++) { o[i][0] = 0.f; o[i][1] = 0.f; o[i][2] = 0.f; o[i][3] = 0.f; }
    const float NEG_INF = __int_as_float(0xff800000);
    float m0 = NEG_INF, m1 = NEG_INF, l0 = 0.f, l1 = 0.f;

    // K/V loaders: 256 threads; row = tid>>2, quad = tid&3 takes 16B chunks
    // at float-col (quad + 4i)*4, i = 0..3.  4 chunks K + 4 chunks V / thread.
    const int ldr = tid >> 2;
    const int ldq = tid & 3;
    const float* Ksrc = Kb + (size_t)ldr * D_MODEL + ldq * 4;
    const float* Vsrc = Vb + (size_t)ldr * D_MODEL + ldq * 4;
    const uint32_t smb = smem_u32(sm);
    const uint32_t kdst0 = smb + (uint32_t)((AT_KS0 + ldr * AT_KP + ldq * 4) * 4);
    const uint32_t kdst1 = smb + (uint32_t)((AT_KS1 + ldr * AT_KP + ldq * 4) * 4);
    const uint32_t vdst0 = smb + (uint32_t)((AT_VS0 + ldr * AT_VP + ldq * 4) * 4);
    const uint32_t vdst1 = smb + (uint32_t)((AT_VS1 + ldr * AT_VP + ldq * 4) * 4);

    #pragma unroll
    for (int i = 0; i < 4; i++) {
        cp_async16(kdst0 + i * 64, Ksrc + i * 16);
        cp_async16(vdst0 + i * 64, Vsrc + i * 16);
    }
    cp_commit();

    // shfl source lanes for C->A fragment conversion
    const int srcl0 = gq * 4 + (tq >> 1);
    const int srcl1 = srcl0 + 2;
    const bool odd = (tq & 1);

    for (int kt = 0; kt < SEQ / 64; kt++) {
        const int buf = kt & 1;
        if (kt + 1 < SEQ / 64) {
            const float* ks2 = Ksrc + (size_t)(kt + 1) * 64 * D_MODEL;
            const float* vs2 = Vsrc + (size_t)(kt + 1) * 64 * D_MODEL;
            const uint32_t kd = buf ? kdst0 : kdst1;
            const uint32_t vd = buf ? vdst0 : vdst1;
            #pragma unroll
            for (int i = 0; i < 4; i++) {
                cp_async16(kd + i * 64, ks2 + i * 16);
                cp_async16(vd + i * 64, vs2 + i * 16);
            }
            cp_commit();
            cp_wait1();
        } else {
            cp_wait0();
        }
        __syncthreads();

        const float* Kst = sm + (buf ? AT_KS1 : AT_KS0);
        const float* Vst = sm + (buf ? AT_VS1 : AT_VS0);

        // ---- S = Q @ K  (both tf32-exact; implicit RZ lossless)
        float s[8][4];
        #pragma unroll
        for (int i = 0; i < 8; i++) { s[i][0] = 0.f; s[i][1] = 0.f; s[i][2] = 0.f; s[i][3] = 0.f; }
        #pragma unroll
        for (int ks = 0; ks < 8; ks++) {
            #pragma unroll
            for (int half = 0; half < 2; half++) {
                uint32_t kb0[4], kb1[4];
                #pragma unroll
                for (int j = 0; j < 4; j++) {
                    const float* kp = Kst + ((half * 4 + j) * 8 + gq) * AT_KP + ks * 8 + tq;
                    kb0[j] = __float_as_uint(kp[0]);
                    kb1[j] = __float_as_uint(kp[4]);
                }
                #pragma unroll
                for (int j = 0; j < 4; j++) {
                    const int nf = half * 4 + j;
                    mma_tf32(s[nf][0], s[nf][1], s[nf][2], s[nf][3],
                             qa[ks][0], qa[ks][1], qa[ks][2], qa[ks][3], kb0[j], kb1[j]);
                }
            }
        }

        // ---- online softmax (row gq -> c0,c1 ; row gq+8 -> c2,c3)
        float mx0 = NEG_INF, mx1 = NEG_INF;
        #pragma unroll
        for (int nf = 0; nf < 8; nf++) {
            mx0 = fmaxf(mx0, fmaxf(s[nf][0], s[nf][1]));
            mx1 = fmaxf(mx1, fmaxf(s[nf][2], s[nf][3]));
        }
        mx0 = fmaxf(mx0, __shfl_xor_sync(0xffffffff, mx0, 1));
        mx0 = fmaxf(mx0, __shfl_xor_sync(0xffffffff, mx0, 2));
        mx1 = fmaxf(mx1, __shfl_xor_sync(0xffffffff, mx1, 1));
        mx1 = fmaxf(mx1, __shfl_xor_sync(0xffffffff, mx1, 2));
        const float m0n = fmaxf(m0, mx0);
        const float m1n = fmaxf(m1, mx1);
        const float fac0 = __expf(m0 - m0n);
        const float fac1 = __expf(m1 - m1n);
        float sum0 = 0.f, sum1 = 0.f;
        // exp, round P to tf32 (rna), accumulate l from the ROUNDED values
        #pragma unroll
        for (int nf = 0; nf < 8; nf++) {
            s[nf][0] = __uint_as_float(f2tf32r(__expf(s[nf][0] - m0n)));
            s[nf][1] = __uint_as_float(f2tf32r(__expf(s[nf][1] - m0n)));
            s[nf][2] = __uint_as_float(f2tf32r(__expf(s[nf][2] - m1n)));
            s[nf][3] = __uint_as_float(f2tf32r(__expf(s[nf][3] - m1n)));
            sum0 += s[nf][0] + s[nf][1];
            sum1 += s[nf][2] + s[nf][3];
        }
        sum0 += __shfl_xor_sync(0xffffffff, sum0, 1);
        sum0 += __shfl_xor_sync(0xffffffff, sum0, 2);
        sum1 += __shfl_xor_sync(0xffffffff, sum1, 1);
        sum1 += __shfl_xor_sync(0xffffffff, sum1, 2);
        m0 = m0n; m1 = m1n;
        l0 = l0 * fac0 + sum0;
        l1 = l1 * fac1 + sum1;

        // ---- rescale O
        #pragma unroll
        for (int nf = 0; nf < 8; nf++) {
            o[nf][0] *= fac0; o[nf][1] *= fac0;
            o[nf][2] *= fac1; o[nf][3] *= fac1;
        }

        // ---- O += P @ V (V tf32-exact) : A-fragments from s[] via shfl
        #pragma unroll
        for (int ks = 0; ks < 8; ks++) {
            const float u0 = __shfl_sync(0xffffffff, s[ks][0], srcl0);
            const float u1 = __shfl_sync(0xffffffff, s[ks][1], srcl0);
            const float u2 = __shfl_sync(0xffffffff, s[ks][2], srcl0);
            const float u3 = __shfl_sync(0xffffffff, s[ks][3], srcl0);
            const float u4 = __shfl_sync(0xffffffff, s[ks][0], srcl1);
            const float u5 = __shfl_sync(0xffffffff, s[ks][1], srcl1);
            const float u6 = __shfl_sync(0xffffffff, s[ks][2], srcl1);
            const float u7 = __shfl_sync(0xffffffff, s[ks][3], srcl1);
            const uint32_t pa0 = __float_as_uint(odd ? u1 : u0);
            const uint32_t pa1 = __float_as_uint(odd ? u3 : u2);
            const uint32_t pa2 = __float_as_uint(odd ? u5 : u4);
            const uint32_t pa3 = __float_as_uint(odd ? u7 : u6);

            #pragma unroll
            for (int half = 0; half < 2; half++) {
                uint32_t vb0[4], vb1[4];
                #pragma unroll
                for (int j = 0; j < 4; j++) {
                    const float* vp = Vst + (ks * 8 + tq) * AT_VP + (half * 4 + j) * 8 + gq;
                    vb0[j] = __float_as_uint(vp[0]);
                    vb1[j] = __float_as_uint(vp[4 * AT_VP]);
                }
                #pragma unroll
                for (int j = 0; j < 4; j++) {
                    const int nf = half * 4 + j;
                    mma_tf32(o[nf][0], o[nf][1], o[nf][2], o[nf][3],
                             pa0, pa1, pa2, pa3, vb0[j], vb1[j]);
                }
            }
        }
        __syncthreads();
    }

    // ---- epilogue: normalize, round to tf32 (lossless read downstream), store
    const float inv0 = 1.f / l0;
    const float inv1 = 1.f / l1;
    float* Ob = Op + (size_t)(b * SEQ + q0 + warp_m + gq) * D_MODEL + h * DK;
    #pragma unroll
    for (int nf = 0; nf < 8; nf++) {
        float2 u, v;
        u.x = __uint_as_float(f2tf32r(o[nf][0] * inv0));
        u.y = __uint_as_float(f2tf32r(o[nf][1] * inv0));
        v.x = __uint_as_float(f2tf32r(o[nf][2] * inv1));
        v.y = __uint_as_float(f2tf32r(o[nf][3] * inv1));
        *(float2*)(Ob + nf * 8 + tq * 2) = u;
        *(float2*)(Ob + (size_t)8 * D_MODEL + nf * 8 + tq * 2) = v;
    }
}

// ============================================================================
// Launcher
// ============================================================================
extern "C" void kernel_launch(void* const* d_in, const int* in_sizes, int n_in,
                              void* d_out, int out_size)
{
    const float* q    = (const float*)d_in[0];
    const float* k    = (const float*)d_in[1];
    const float* v    = (const float*)d_in[2];
    const float* wq_w = (const float*)d_in[3];
    const float* wq_b = (const float*)d_in[4];
    const float* wk_w = (const float*)d_in[5];
    const float* wk_b = (const float*)d_in[6];
    const float* wv_w = (const float*)d_in[7];
    const float* wv_b = (const float*)d_in[8];
    const float* wo_w = (const float*)d_in[9];
    const float* wo_b = (const float*)d_in[10];

    float *gq, *gk, *gv, *ga, *wq, *wk, *wv, *wo;
    cudaGetSymbolAddress((void**)&gq, g_q);
    cudaGetSymbolAddress((void**)&gk, g_k);
    cudaGetSymbolAddress((void**)&gv, g_v);
    cudaGetSymbolAddress((void**)&ga, g_att);
    cudaGetSymbolAddress((void**)&wq, g_wq);
    cudaGetSymbolAddress((void**)&wk, g_wk);
    cudaGetSymbolAddress((void**)&wv, g_wv);
    cudaGetSymbolAddress((void**)&wo, g_wo);

    cudaFuncSetAttribute(gemm_mma, cudaFuncAttributeMaxDynamicSharedMemorySize,
                         SMEM_GEMM_BYTES);
    cudaFuncSetAttribute(attn_mma, cudaFuncAttributeMaxDynamicSharedMemorySize,
                         AT_SMEM_BYTES);

    // Pre-round all four weight matrices to tf32 (one pass, ~16MB traffic).
    const int wgrid = (D_MODEL * D_MODEL) / (256 * 4);   // 1024
    round_w<<<wgrid, 256>>>(wq_w, wq);
    round_w<<<wgrid, 256>>>(wk_w, wk);
    round_w<<<wgrid, 256>>>(wv_w, wv);
    round_w<<<wgrid, 256>>>(wo_w, wo);

    dim3 gemm_grid(D_MODEL / BN, MTOT / BM);   // (8, 32)

    // Q/K/V projections: outputs rounded to tf32 (rna) in the epilogue.
    gemm_mma<<<gemm_grid, 256, SMEM_GEMM_BYTES>>>(q, wq, wq_b, gq, MTOT, D_MODEL, D_MODEL, 1);
    gemm_mma<<<gemm_grid, 256, SMEM_GEMM_BYTES>>>(k, wk, wk_b, gk, MTOT, D_MODEL, D_MODEL, 1);
    gemm_mma<<<gemm_grid, 256, SMEM_GEMM_BYTES>>>(v, wv, wv_b, gv, MTOT, D_MODEL, D_MODEL, 1);

    attn_mma<<<dim3(SEQ / 128, BATCH * NHEAD), 256, AT_SMEM_BYTES>>>(gq, gk, gv, ga);

    // Output projection: full precision store (attn output already tf32-exact).
    gemm_mma<<<gemm_grid, 256, SMEM_GEMM_BYTES>>>(ga, wo, wo_b, (float*)d_out, MTOT, D_MODEL, D_MODEL, 0);
}